// round 2
// baseline (speedup 1.0000x reference)
#include <cuda_runtime.h>
#include <math.h>

#define BB   128
#define NN   1024
#define DIN  192
#define HH   128
#define KK   3

// -------- device scratch (no allocations allowed) --------
__device__ float g_k[(size_t)BB*NN*HH];      // 64 MB
__device__ float g_v[(size_t)BB*NN*HH];      // 64 MB
__device__ float g_slots[BB*KK*HH];

// ============================================================
// Kernel 1: inputs = LN(patch @ Wp^T + bp); k = inputs@Wk^T+bk; v = inputs@Wv^T+bv
// BM=64 rows per block, 256 threads (16x16), micro-tile 4x8.
// ============================================================
#define BM 64
#define AS_STRIDE 193
#define WT_STRIDE 132
#define LS_STRIDE 132
#define AS_SIZE (BM*AS_STRIDE)      // 12352 floats
#define WT_SIZE (64*WT_STRIDE)      // 8448 floats
#define LS_SIZE (BM*LS_STRIDE)      // 8448 floats
#define SM1_FLOATS (AS_SIZE + WT_SIZE + LS_SIZE)

__global__ __launch_bounds__(256) void fused_proj_ln_kv(
    const float* __restrict__ patch,
    const float* __restrict__ Wp, const float* __restrict__ bp,
    const float* __restrict__ g_in, const float* __restrict__ b_in,
    const float* __restrict__ Wk, const float* __restrict__ bk,
    const float* __restrict__ Wv, const float* __restrict__ bv)
{
    extern __shared__ float sm[];
    float* As = sm;                       // [64][193]
    float* Wt = sm + AS_SIZE;             // [64][132] transposed weight chunk
    float* Ls = sm + AS_SIZE + WT_SIZE;   // [64][132] LN'ed inputs tile

    const int t  = threadIdx.x;
    const int tx = t & 15;
    const int ty = t >> 4;
    const int ty4 = ty * 4;
    const int j0 = tx * 8;
    const long rowbase = (long)blockIdx.x * BM;

    // ---- load patch tile (64 x 192) ----
    for (int q4 = t; q4 < BM * (DIN/4); q4 += 256) {
        int row = q4 / (DIN/4);
        int c4  = q4 % (DIN/4);
        float4 g = *reinterpret_cast<const float4*>(patch + (rowbase + row)*DIN + c4*4);
        float* dst = &As[row*AS_STRIDE + c4*4];
        dst[0] = g.x; dst[1] = g.y; dst[2] = g.z; dst[3] = g.w;
    }

    float acc[4][8];
    #pragma unroll
    for (int r = 0; r < 4; r++)
        #pragma unroll
        for (int u = 0; u < 8; u++) acc[r][u] = 0.0f;

    // ---- phase 1: P = patch @ Wp^T, K=192 in 3 chunks of 64 ----
    for (int c = 0; c < 3; c++) {
        __syncthreads();  // protect Wt (and As on first pass)
        for (int idx = t; idx < 2048; idx += 256) {  // idx = j*16 + i4
            int j  = idx >> 4;
            int i4 = idx & 15;
            float4 w = *reinterpret_cast<const float4*>(Wp + j*DIN + c*64 + i4*4);
            int ib = i4*4;
            Wt[(ib+0)*WT_STRIDE + j] = w.x;
            Wt[(ib+1)*WT_STRIDE + j] = w.y;
            Wt[(ib+2)*WT_STRIDE + j] = w.z;
            Wt[(ib+3)*WT_STRIDE + j] = w.w;
        }
        __syncthreads();
        #pragma unroll 4
        for (int i = 0; i < 64; i++) {
            float a0 = As[(ty4+0)*AS_STRIDE + c*64 + i];
            float a1 = As[(ty4+1)*AS_STRIDE + c*64 + i];
            float a2 = As[(ty4+2)*AS_STRIDE + c*64 + i];
            float a3 = As[(ty4+3)*AS_STRIDE + c*64 + i];
            float4 bA = *reinterpret_cast<float4*>(&Wt[i*WT_STRIDE + j0]);
            float4 bBv = *reinterpret_cast<float4*>(&Wt[i*WT_STRIDE + j0 + 4]);
            float bv8[8] = {bA.x, bA.y, bA.z, bA.w, bBv.x, bBv.y, bBv.z, bBv.w};
            #pragma unroll
            for (int u = 0; u < 8; u++) {
                acc[0][u] += a0 * bv8[u];
                acc[1][u] += a1 * bv8[u];
                acc[2][u] += a2 * bv8[u];
                acc[3][u] += a3 * bv8[u];
            }
        }
    }

    // ---- LayerNorm epilogue (rows owned by 16 consecutive lanes) ----
    {
        float bpv[8], gv[8], bvv[8];
        #pragma unroll
        for (int u = 0; u < 8; u++) {
            bpv[u] = bp[j0+u]; gv[u] = g_in[j0+u]; bvv[u] = b_in[j0+u];
        }
        #pragma unroll
        for (int r = 0; r < 4; r++) {
            float cv[8];
            float s = 0.0f, sq = 0.0f;
            #pragma unroll
            for (int u = 0; u < 8; u++) {
                float x = acc[r][u] + bpv[u];
                cv[u] = x; s += x; sq += x*x;
            }
            #pragma unroll
            for (int m = 8; m >= 1; m >>= 1) {
                s  += __shfl_xor_sync(0xffffffffu, s,  m);
                sq += __shfl_xor_sync(0xffffffffu, sq, m);
            }
            float mu   = s  * (1.0f/128.0f);
            float var  = sq * (1.0f/128.0f) - mu*mu;
            float rstd = rsqrtf(var + 1e-5f);
            #pragma unroll
            for (int u = 0; u < 8; u++)
                Ls[(ty4+r)*LS_STRIDE + j0 + u] = (cv[u]-mu)*rstd*gv[u] + bvv[u];
        }
    }
    __syncthreads();

    // ---- phase 2: k and v GEMMs over LN tile ----
    for (int pass = 0; pass < 2; pass++) {
        const float* W    = pass ? Wv : Wk;
        const float* bias = pass ? bv : bk;
        float* outp       = pass ? g_v : g_k;

        float acc2[4][8];
        #pragma unroll
        for (int r = 0; r < 4; r++)
            #pragma unroll
            for (int u = 0; u < 8; u++) acc2[r][u] = 0.0f;

        for (int c = 0; c < 2; c++) {
            __syncthreads();
            for (int idx = t; idx < 2048; idx += 256) {
                int j  = idx >> 4;
                int i4 = idx & 15;
                float4 w = *reinterpret_cast<const float4*>(W + j*HH + c*64 + i4*4);
                int ib = i4*4;
                Wt[(ib+0)*WT_STRIDE + j] = w.x;
                Wt[(ib+1)*WT_STRIDE + j] = w.y;
                Wt[(ib+2)*WT_STRIDE + j] = w.z;
                Wt[(ib+3)*WT_STRIDE + j] = w.w;
            }
            __syncthreads();
            #pragma unroll 4
            for (int i = 0; i < 64; i++) {
                float a0 = Ls[(ty4+0)*LS_STRIDE + c*64 + i];
                float a1 = Ls[(ty4+1)*LS_STRIDE + c*64 + i];
                float a2 = Ls[(ty4+2)*LS_STRIDE + c*64 + i];
                float a3 = Ls[(ty4+3)*LS_STRIDE + c*64 + i];
                float4 bA = *reinterpret_cast<float4*>(&Wt[i*WT_STRIDE + j0]);
                float4 bBv = *reinterpret_cast<float4*>(&Wt[i*WT_STRIDE + j0 + 4]);
                float bv8[8] = {bA.x, bA.y, bA.z, bA.w, bBv.x, bBv.y, bBv.z, bBv.w};
                #pragma unroll
                for (int u = 0; u < 8; u++) {
                    acc2[0][u] += a0 * bv8[u];
                    acc2[1][u] += a1 * bv8[u];
                    acc2[2][u] += a2 * bv8[u];
                    acc2[3][u] += a3 * bv8[u];
                }
            }
        }
        float bb[8];
        #pragma unroll
        for (int u = 0; u < 8; u++) bb[u] = bias[j0+u];
        #pragma unroll
        for (int r = 0; r < 4; r++) {
            float4 o1 = make_float4(acc2[r][0]+bb[0], acc2[r][1]+bb[1],
                                    acc2[r][2]+bb[2], acc2[r][3]+bb[3]);
            float4 o2 = make_float4(acc2[r][4]+bb[4], acc2[r][5]+bb[5],
                                    acc2[r][6]+bb[6], acc2[r][7]+bb[7]);
            float* dst = outp + (rowbase + ty4 + r)*HH + j0;
            *reinterpret_cast<float4*>(dst)     = o1;
            *reinterpret_cast<float4*>(dst + 4) = o2;
        }
    }
}

// ============================================================
// Kernel 2: slots = slot_mu + exp(slot_log_sigma) * noise
// ============================================================
__global__ void init_slots(const float* __restrict__ noise,
                           const float* __restrict__ mu,
                           const float* __restrict__ ls)
{
    int i = blockIdx.x * 256 + threadIdx.x;
    if (i < BB*KK*HH) {
        int r = i % (KK*HH);
        g_slots[i] = mu[r] + expf(ls[r]) * noise[i];
    }
}

// ============================================================
// Kernel 3: one slot-attention iteration. One block per batch.
// ============================================================
#define SM2_FLOATS 22720

__global__ __launch_bounds__(256) void slot_iter(
    const float* __restrict__ Wq,  const float* __restrict__ bq,
    const float* __restrict__ g_s, const float* __restrict__ b_s,
    const float* __restrict__ Wih, const float* __restrict__ bih,
    const float* __restrict__ Whh, const float* __restrict__ bhh,
    const float* __restrict__ g_m, const float* __restrict__ b_m,
    const float* __restrict__ W1,  const float* __restrict__ b1,
    const float* __restrict__ W2,  const float* __restrict__ b2,
    float* __restrict__ out_slots, float* __restrict__ out_attn)
{
    extern __shared__ float sm[];
    float* kbuf   = sm;            // [64][128]
    float* vbuf   = sm + 8192;     // [64][128]
    float* h_prev = sm + 16384;    // [3][128]
    float* s_ln   = h_prev + 384;  // [3][128]
    float* q_s    = s_ln + 384;    // [3][128] (pre-scaled)
    float* attn_s = q_s + 384;     // [3][64]
    float* updp   = attn_s + 192;  // [2][3][128]
    float* updf   = updp + 768;    // [3][128]
    float* gi_s   = updf + 384;    // [3][384]
    float* gh_s   = gi_s + 1152;   // [3][384]
    float* snew   = gh_s + 1152;   // [3][128]
    float* hm     = snew + 384;    // [3][128]
    float* a1_s   = hm + 384;      // [3][256]

    const int t = threadIdx.x;
    const int lane = t & 31;
    const int warp = t >> 5;
    const int b = blockIdx.x;

    // 1. load slots (= h for GRU)
    for (int i = t; i < KK*HH; i += 256) h_prev[i] = g_slots[b*KK*HH + i];
    __syncthreads();

    // 2. s = LN(slots)*g_s + b_s  (one warp per slot row)
    if (warp < KK) {
        float x[4];
        float s = 0.0f, sq = 0.0f;
        #pragma unroll
        for (int m = 0; m < 4; m++) {
            x[m] = h_prev[warp*128 + lane + 32*m];
            s += x[m]; sq += x[m]*x[m];
        }
        #pragma unroll
        for (int off = 16; off >= 1; off >>= 1) {
            s  += __shfl_xor_sync(0xffffffffu, s,  off);
            sq += __shfl_xor_sync(0xffffffffu, sq, off);
        }
        float mu   = s  * (1.0f/128.0f);
        float var  = sq * (1.0f/128.0f) - mu*mu;
        float rstd = rsqrtf(var + 1e-5f);
        #pragma unroll
        for (int m = 0; m < 4; m++) {
            int c = lane + 32*m;
            s_ln[warp*128 + c] = (x[m]-mu)*rstd*g_s[c] + b_s[c];
        }
    }
    __syncthreads();

    // 3. q = (s @ Wq^T + bq) * scale
    if (t < 128) {
        float a0 = 0.f, a1 = 0.f, a2 = 0.f;
        const float* w = Wq + t*128;
        #pragma unroll 4
        for (int i = 0; i < 128; i++) {
            float wv = w[i];
            a0 += s_ln[i]       * wv;
            a1 += s_ln[128 + i] * wv;
            a2 += s_ln[256 + i] * wv;
        }
        const float sc = 0.08838834764831843f;  // 1/sqrt(128)
        float bqv = bq[t];
        q_s[t]       = (a0 + bqv) * sc;
        q_s[128 + t] = (a1 + bqv) * sc;
        q_s[256 + t] = (a2 + bqv) * sc;
    }
    __syncthreads();

    // preload q for logits (lane-strided)
    float qr[3][4];
    #pragma unroll
    for (int kk = 0; kk < 3; kk++)
        #pragma unroll
        for (int m = 0; m < 4; m++)
            qr[kk][m] = q_s[kk*128 + lane + 32*m];

    const int half = t >> 7;
    const int j    = t & 127;
    float u0 = 0.f, u1 = 0.f, u2 = 0.f;   // register-resident updates

    const float* kb = g_k + (size_t)b * NN * HH;
    const float* vb = g_v + (size_t)b * NN * HH;

    // 4. attention loop over N in tiles of 64
    for (int n0 = 0; n0 < NN; n0 += 64) {
        __syncthreads();  // previous tile fully consumed
        {
            const float4* ks4 = reinterpret_cast<const float4*>(kb + (size_t)n0*HH);
            const float4* vs4 = reinterpret_cast<const float4*>(vb + (size_t)n0*HH);
            float4* kd = reinterpret_cast<float4*>(kbuf);
            float4* vd = reinterpret_cast<float4*>(vbuf);
            for (int i = t; i < 2048; i += 256) { kd[i] = ks4[i]; vd[i] = vs4[i]; }
        }
        __syncthreads();

        // logits + softmax over K=3 (warp w handles 8 rows)
        #pragma unroll
        for (int s8 = 0; s8 < 8; s8++) {
            int nl = warp*8 + s8;
            const float* kr = kbuf + nl*128;
            float p0 = 0.f, p1 = 0.f, p2 = 0.f;
            #pragma unroll
            for (int m = 0; m < 4; m++) {
                float kvv = kr[lane + 32*m];
                p0 += kvv * qr[0][m];
                p1 += kvv * qr[1][m];
                p2 += kvv * qr[2][m];
            }
            #pragma unroll
            for (int off = 16; off >= 1; off >>= 1) {
                p0 += __shfl_xor_sync(0xffffffffu, p0, off);
                p1 += __shfl_xor_sync(0xffffffffu, p1, off);
                p2 += __shfl_xor_sync(0xffffffffu, p2, off);
            }
            if (lane == 0) {
                float mx = fmaxf(p0, fmaxf(p1, p2));
                float e0 = expf(p0 - mx), e1 = expf(p1 - mx), e2 = expf(p2 - mx);
                float inv = 1.0f / (e0 + e1 + e2);
                float a0 = e0*inv, a1 = e1*inv, a2 = e2*inv;
                attn_s[nl]       = a0;
                attn_s[64 + nl]  = a1;
                attn_s[128 + nl] = a2;
                int gbase = (b*KK)*NN + n0 + nl;
                out_attn[gbase]        = a0;
                out_attn[gbase + NN]   = a1;
                out_attn[gbase + 2*NN] = a2;
            }
        }
        __syncthreads();

        // updates accumulation (split n-range by half)
        #pragma unroll 4
        for (int n = half*32; n < half*32 + 32; n++) {
            float vv = vbuf[n*128 + j];
            u0 += attn_s[n]       * vv;
            u1 += attn_s[64 + n]  * vv;
            u2 += attn_s[128 + n] * vv;
        }
    }
    updp[half*384 +        j] = u0;
    updp[half*384 + 128  + j] = u1;
    updp[half*384 + 256  + j] = u2;
    __syncthreads();
    if (t < 128) {
        updf[t]       = updp[t]       + updp[384 + t];
        updf[128 + t] = updp[128 + t] + updp[384 + 128 + t];
        updf[256 + t] = updp[256 + t] + updp[384 + 256 + t];
    }
    __syncthreads();

    // 5. GRU gate GEMMs: gi = updates@Wih^T+bih, gh = h_prev@Whh^T+bhh
    for (int jj = t; jj < 384; jj += 256) {
        float ai0=0.f, ai1=0.f, ai2=0.f, ah0=0.f, ah1=0.f, ah2=0.f;
        const float* wi = Wih + jj*128;
        const float* wh = Whh + jj*128;
        #pragma unroll 4
        for (int i = 0; i < 128; i++) {
            float wiv = wi[i], whv = wh[i];
            ai0 += updf[i]        * wiv;
            ai1 += updf[128 + i]  * wiv;
            ai2 += updf[256 + i]  * wiv;
            ah0 += h_prev[i]       * whv;
            ah1 += h_prev[128 + i] * whv;
            ah2 += h_prev[256 + i] * whv;
        }
        float bi = bih[jj], bh = bhh[jj];
        gi_s[jj]        = ai0 + bi;
        gi_s[384 + jj]  = ai1 + bi;
        gi_s[768 + jj]  = ai2 + bi;
        gh_s[jj]        = ah0 + bh;
        gh_s[384 + jj]  = ah1 + bh;
        gh_s[768 + jj]  = ah2 + bh;
    }
    __syncthreads();

    // 6. gate combine
    if (t < 128) {
        #pragma unroll
        for (int kk = 0; kk < 3; kk++) {
            float ir  = gi_s[kk*384 + t];
            float iz  = gi_s[kk*384 + 128 + t];
            float inn = gi_s[kk*384 + 256 + t];
            float hr  = gh_s[kk*384 + t];
            float hz  = gh_s[kk*384 + 128 + t];
            float hn  = gh_s[kk*384 + 256 + t];
            float r = 1.0f / (1.0f + expf(-(ir + hr)));
            float z = 1.0f / (1.0f + expf(-(iz + hz)));
            float nn = tanhf(inn + r*hn);
            snew[kk*128 + t] = (1.0f - z)*nn + z*h_prev[kk*128 + t];
        }
    }
    __syncthreads();

    // 7. hm = LN(snew)*g_m + b_m
    if (warp < KK) {
        float x[4];
        float s = 0.0f, sq = 0.0f;
        #pragma unroll
        for (int m = 0; m < 4; m++) {
            x[m] = snew[warp*128 + lane + 32*m];
            s += x[m]; sq += x[m]*x[m];
        }
        #pragma unroll
        for (int off = 16; off >= 1; off >>= 1) {
            s  += __shfl_xor_sync(0xffffffffu, s,  off);
            sq += __shfl_xor_sync(0xffffffffu, sq, off);
        }
        float mu   = s  * (1.0f/128.0f);
        float var  = sq * (1.0f/128.0f) - mu*mu;
        float rstd = rsqrtf(var + 1e-5f);
        #pragma unroll
        for (int m = 0; m < 4; m++) {
            int c = lane + 32*m;
            hm[warp*128 + c] = (x[m]-mu)*rstd*g_m[c] + b_m[c];
        }
    }
    __syncthreads();

    // 8. a1 = gelu_exact(hm @ W1^T + b1)   (256 output cols, all threads)
    {
        float a0 = 0.f, a1v = 0.f, a2 = 0.f;
        const float* w = W1 + t*128;
        #pragma unroll 4
        for (int i = 0; i < 128; i++) {
            float wv = w[i];
            a0  += hm[i]       * wv;
            a1v += hm[128 + i] * wv;
            a2  += hm[256 + i] * wv;
        }
        float bb = b1[t];
        float x0 = a0 + bb, x1 = a1v + bb, x2 = a2 + bb;
        const float is2 = 0.70710678118654752f;
        a1_s[t]        = 0.5f * x0 * (1.0f + erff(x0 * is2));
        a1_s[256 + t]  = 0.5f * x1 * (1.0f + erff(x1 * is2));
        a1_s[512 + t]  = 0.5f * x2 * (1.0f + erff(x2 * is2));
    }
    __syncthreads();

    // 9. slots_out = snew + a1 @ W2^T + b2
    if (t < 128) {
        float a0 = 0.f, a1v = 0.f, a2 = 0.f;
        const float* w = W2 + t*256;
        #pragma unroll 4
        for (int i = 0; i < 256; i++) {
            float wv = w[i];
            a0  += a1_s[i]       * wv;
            a1v += a1_s[256 + i] * wv;
            a2  += a1_s[512 + i] * wv;
        }
        float bb = b2[t];
        int base = b*KK*HH;
        float f0 = snew[t]       + a0  + bb;
        float f1 = snew[128 + t] + a1v + bb;
        float f2 = snew[256 + t] + a2  + bb;
        g_slots[base + t]       = f0;  out_slots[base + t]       = f0;
        g_slots[base + 128 + t] = f1;  out_slots[base + 128 + t] = f1;
        g_slots[base + 256 + t] = f2;  out_slots[base + 256 + t] = f2;
    }
}

// ============================================================
extern "C" void kernel_launch(void* const* d_in, const int* in_sizes, int n_in,
                              void* d_out, int out_size)
{
    const float* patch   = (const float*)d_in[0];
    const float* noise   = (const float*)d_in[1];
    const float* slot_mu = (const float*)d_in[2];
    const float* slot_ls = (const float*)d_in[3];
    const float* Wp  = (const float*)d_in[4];
    const float* bp  = (const float*)d_in[5];
    const float* g_in= (const float*)d_in[6];
    const float* b_in= (const float*)d_in[7];
    const float* Wq  = (const float*)d_in[8];
    const float* bq  = (const float*)d_in[9];
    const float* Wk  = (const float*)d_in[10];
    const float* bk  = (const float*)d_in[11];
    const float* Wv  = (const float*)d_in[12];
    const float* bv  = (const float*)d_in[13];
    const float* Wih = (const float*)d_in[14];
    const float* bih = (const float*)d_in[15];
    const float* Whh = (const float*)d_in[16];
    const float* bhh = (const float*)d_in[17];
    const float* g_s = (const float*)d_in[18];
    const float* b_s = (const float*)d_in[19];
    const float* W1  = (const float*)d_in[20];
    const float* b1  = (const float*)d_in[21];
    const float* W2  = (const float*)d_in[22];
    const float* b2  = (const float*)d_in[23];
    const float* g_m = (const float*)d_in[24];
    const float* b_m = (const float*)d_in[25];

    float* out       = (float*)d_out;
    float* out_slots = out;                     // B*K*H = 49152
    float* out_attn  = out + BB*KK*HH;          // B*K*N = 393216

    const size_t SM1 = SM1_FLOATS * sizeof(float);   // ~114 KB
    const size_t SM2 = SM2_FLOATS * sizeof(float);   // ~89 KB
    cudaFuncSetAttribute(fused_proj_ln_kv, cudaFuncAttributeMaxDynamicSharedMemorySize, (int)SM1);
    cudaFuncSetAttribute(slot_iter,        cudaFuncAttributeMaxDynamicSharedMemorySize, (int)SM2);

    fused_proj_ln_kv<<<(BB*NN)/BM, 256, SM1>>>(patch, Wp, bp, g_in, b_in, Wk, bk, Wv, bv);
    init_slots<<<(BB*KK*HH + 255)/256, 256>>>(noise, slot_mu, slot_ls);
    for (int it = 0; it < 3; it++) {
        slot_iter<<<BB, 256, SM2>>>(Wq, bq, g_s, b_s, Wih, bih, Whh, bhh,
                                    g_m, b_m, W1, b1, W2, b2,
                                    out_slots, out_attn);
    }
}

// round 7
// speedup vs baseline: 1.4307x; 1.4307x over previous
#include <cuda_runtime.h>
#include <math.h>

#define BB   128
#define NN   1024
#define DIN  192
#define HH   128
#define KK   3
#define NTILES 8
#define TILE_N 128

typedef unsigned long long ull;

// -------- device scratch (no allocations allowed) --------
__device__ float g_k[(size_t)BB*NN*HH];      // 64 MB
__device__ float g_v[(size_t)BB*NN*HH];      // 64 MB
__device__ float g_slots[BB*KK*HH];
__device__ float g_q[BB*KK*HH];
__device__ float g_updp[BB*NTILES*KK*HH];    // partial updates, 1.5 MB

// ---------------- f32x2 helpers ----------------
__device__ __forceinline__ ull ffma2(ull a, ull b, ull c) {
    ull d;
    asm("fma.rn.f32x2 %0, %1, %2, %3;" : "=l"(d) : "l"(a), "l"(b), "l"(c));
    return d;
}
__device__ __forceinline__ ull pack2(float x) {
    ull d;
    unsigned xi = __float_as_uint(x);
    asm("mov.b64 %0, {%1, %1};" : "=l"(d) : "r"(xi));
    return d;
}
__device__ __forceinline__ void unpack2(ull v, float& lo, float& hi) {
    unsigned a, b;
    asm("mov.b64 {%0, %1}, %2;" : "=r"(a), "=r"(b) : "l"(v));
    lo = __uint_as_float(a); hi = __uint_as_float(b);
}

// ============================================================
// Kernel 1: inputs = LN(patch @ Wp^T + bp); k = inputs@Wk^T; v = inputs@Wv^T
// BM=128 rows/block, 256 threads (16x16), micro-tile 8x8, FFMA2 inner loop.
// ============================================================
#define BM 128
#define AS_STRIDE 68            // 64-col chunk + pad; 8*68%32!=... ty-delta=1*68%32=4 -> no conflict
#define WT_STRIDE 132
#define LS_STRIDE 132
#define AS_SIZE (BM*AS_STRIDE)      // 8704
#define WT_SIZE (64*WT_STRIDE)      // 8448
#define LS_SIZE (BM*LS_STRIDE)      // 16896
#define SM1_FLOATS (AS_SIZE + WT_SIZE + LS_SIZE)   // 34048 floats = 136 KB

__global__ __launch_bounds__(256) void fused_proj_ln_kv(
    const float* __restrict__ patch,
    const float* __restrict__ Wp, const float* __restrict__ bp,
    const float* __restrict__ g_in, const float* __restrict__ b_in,
    const float* __restrict__ Wk, const float* __restrict__ bk,
    const float* __restrict__ Wv, const float* __restrict__ bv)
{
    extern __shared__ float sm[];
    float* As = sm;                       // [128][68]  current 64-col patch chunk
    float* Wt = sm + AS_SIZE;             // [64][132]  transposed weight chunk
    float* Ls = sm + AS_SIZE + WT_SIZE;   // [128][132] LN'ed inputs tile (full 128 cols)

    const int t  = threadIdx.x;
    const int tx = t & 15;
    const int ty = t >> 4;
    const int j0 = tx * 8;
    const long rowbase = (long)blockIdx.x * BM;

    ull acc[8][4];
    #pragma unroll
    for (int r = 0; r < 8; r++)
        #pragma unroll
        for (int u = 0; u < 4; u++) acc[r][u] = 0ull;

    // ---- phase 1: P = patch @ Wp^T, K=192 in 3 chunks of 64 ----
    for (int c = 0; c < 3; c++) {
        __syncthreads();
        // load patch chunk (128 x 64) -> As
        for (int q4 = t; q4 < BM * 16; q4 += 256) {
            int row = q4 >> 4;
            int c4  = q4 & 15;
            float4 g = *reinterpret_cast<const float4*>(patch + (rowbase + row)*DIN + c*64 + c4*4);
            *reinterpret_cast<float4*>(&As[row*AS_STRIDE + c4*4]) = g;
        }
        // load weight chunk transposed -> Wt
        for (int idx = t; idx < 2048; idx += 256) {
            int j  = idx >> 4;
            int i4 = idx & 15;
            float4 w = *reinterpret_cast<const float4*>(Wp + j*DIN + c*64 + i4*4);
            int ib = i4*4;
            Wt[(ib+0)*WT_STRIDE + j] = w.x;
            Wt[(ib+1)*WT_STRIDE + j] = w.y;
            Wt[(ib+2)*WT_STRIDE + j] = w.z;
            Wt[(ib+3)*WT_STRIDE + j] = w.w;
        }
        __syncthreads();
        #pragma unroll 4
        for (int i = 0; i < 64; i++) {
            ulonglong2 b0 = *reinterpret_cast<ulonglong2*>(&Wt[i*WT_STRIDE + j0]);
            ulonglong2 b1 = *reinterpret_cast<ulonglong2*>(&Wt[i*WT_STRIDE + j0 + 4]);
            #pragma unroll
            for (int r = 0; r < 8; r++) {
                ull av = pack2(As[(ty + 16*r)*AS_STRIDE + i]);
                acc[r][0] = ffma2(av, b0.x, acc[r][0]);
                acc[r][1] = ffma2(av, b0.y, acc[r][1]);
                acc[r][2] = ffma2(av, b1.x, acc[r][2]);
                acc[r][3] = ffma2(av, b1.y, acc[r][3]);
            }
        }
    }

    // ---- LayerNorm epilogue ----
    {
        float bpv[8], gv[8], bvv[8];
        #pragma unroll
        for (int u = 0; u < 8; u++) {
            bpv[u] = bp[j0+u]; gv[u] = g_in[j0+u]; bvv[u] = b_in[j0+u];
        }
        #pragma unroll
        for (int r = 0; r < 8; r++) {
            float cv[8];
            #pragma unroll
            for (int u = 0; u < 4; u++) unpack2(acc[r][u], cv[2*u], cv[2*u+1]);
            float s = 0.0f, sq = 0.0f;
            #pragma unroll
            for (int u = 0; u < 8; u++) {
                float x = cv[u] + bpv[u];
                cv[u] = x; s += x; sq += x*x;
            }
            #pragma unroll
            for (int m = 8; m >= 1; m >>= 1) {
                s  += __shfl_xor_sync(0xffffffffu, s,  m);
                sq += __shfl_xor_sync(0xffffffffu, sq, m);
            }
            float mu   = s  * (1.0f/128.0f);
            float var  = sq * (1.0f/128.0f) - mu*mu;
            float rstd = rsqrtf(var + 1e-5f);
            #pragma unroll
            for (int u = 0; u < 8; u++)
                Ls[(ty + 16*r)*LS_STRIDE + j0 + u] = (cv[u]-mu)*rstd*gv[u] + bvv[u];
        }
    }

    // ---- phase 2: k and v GEMMs over LN tile ----
    for (int pass = 0; pass < 2; pass++) {
        const float* W    = pass ? Wv : Wk;
        const float* bias = pass ? bv : bk;
        float* outp       = pass ? g_v : g_k;

        #pragma unroll
        for (int r = 0; r < 8; r++)
            #pragma unroll
            for (int u = 0; u < 4; u++) acc[r][u] = 0ull;

        for (int c = 0; c < 2; c++) {
            __syncthreads();
            for (int idx = t; idx < 2048; idx += 256) {
                int j  = idx >> 4;
                int i4 = idx & 15;
                float4 w = *reinterpret_cast<const float4*>(W + j*HH + c*64 + i4*4);
                int ib = i4*4;
                Wt[(ib+0)*WT_STRIDE + j] = w.x;
                Wt[(ib+1)*WT_STRIDE + j] = w.y;
                Wt[(ib+2)*WT_STRIDE + j] = w.z;
                Wt[(ib+3)*WT_STRIDE + j] = w.w;
            }
            __syncthreads();
            #pragma unroll 4
            for (int i = 0; i < 64; i++) {
                ulonglong2 b0 = *reinterpret_cast<ulonglong2*>(&Wt[i*WT_STRIDE + j0]);
                ulonglong2 b1 = *reinterpret_cast<ulonglong2*>(&Wt[i*WT_STRIDE + j0 + 4]);
                #pragma unroll
                for (int r = 0; r < 8; r++) {
                    ull av = pack2(Ls[(ty + 16*r)*LS_STRIDE + c*64 + i]);
                    acc[r][0] = ffma2(av, b0.x, acc[r][0]);
                    acc[r][1] = ffma2(av, b0.y, acc[r][1]);
                    acc[r][2] = ffma2(av, b1.x, acc[r][2]);
                    acc[r][3] = ffma2(av, b1.y, acc[r][3]);
                }
            }
        }
        float bb[8];
        #pragma unroll
        for (int u = 0; u < 8; u++) bb[u] = bias[j0+u];
        #pragma unroll
        for (int r = 0; r < 8; r++) {
            float cv[8];
            #pragma unroll
            for (int u = 0; u < 4; u++) unpack2(acc[r][u], cv[2*u], cv[2*u+1]);
            float4 o1 = make_float4(cv[0]+bb[0], cv[1]+bb[1], cv[2]+bb[2], cv[3]+bb[3]);
            float4 o2 = make_float4(cv[4]+bb[4], cv[5]+bb[5], cv[6]+bb[6], cv[7]+bb[7]);
            float* dst = outp + (rowbase + ty + 16*r)*HH + j0;
            *reinterpret_cast<float4*>(dst)     = o1;
            *reinterpret_cast<float4*>(dst + 4) = o2;
        }
    }
}

// ============================================================
// Kernel 2: slots = slot_mu + exp(slot_log_sigma) * noise
// ============================================================
__global__ void init_slots(const float* __restrict__ noise,
                           const float* __restrict__ mu,
                           const float* __restrict__ ls)
{
    int i = blockIdx.x * 256 + threadIdx.x;
    if (i < BB*KK*HH) {
        int r = i % (KK*HH);
        g_slots[i] = mu[r] + expf(ls[r]) * noise[i];
    }
}

// ============================================================
// compute_q: q = (LN(slots)*g_s + b_s) @ Wq^T + bq, pre-scaled. grid=BB, 128 thr.
// ============================================================
__global__ __launch_bounds__(128) void compute_q(
    const float* __restrict__ Wq,  const float* __restrict__ bq,
    const float* __restrict__ g_s, const float* __restrict__ b_s)
{
    __shared__ float h[384];
    __shared__ float s_ln[384];
    const int t = threadIdx.x;
    const int lane = t & 31;
    const int warp = t >> 5;
    const int b = blockIdx.x;

    for (int i = t; i < 384; i += 128) h[i] = g_slots[b*384 + i];
    __syncthreads();

    if (warp < KK) {
        float x[4];
        float s = 0.0f, sq = 0.0f;
        #pragma unroll
        for (int m = 0; m < 4; m++) {
            x[m] = h[warp*128 + lane + 32*m];
            s += x[m]; sq += x[m]*x[m];
        }
        #pragma unroll
        for (int off = 16; off >= 1; off >>= 1) {
            s  += __shfl_xor_sync(0xffffffffu, s,  off);
            sq += __shfl_xor_sync(0xffffffffu, sq, off);
        }
        float mu   = s  * (1.0f/128.0f);
        float var  = sq * (1.0f/128.0f) - mu*mu;
        float rstd = rsqrtf(var + 1e-5f);
        #pragma unroll
        for (int m = 0; m < 4; m++) {
            int c = lane + 32*m;
            s_ln[warp*128 + c] = (x[m]-mu)*rstd*g_s[c] + b_s[c];
        }
    }
    __syncthreads();

    float a0 = 0.f, a1 = 0.f, a2 = 0.f;
    const float* w = Wq + t*128;
    #pragma unroll 4
    for (int i = 0; i < 128; i++) {
        float wv = w[i];
        a0 += s_ln[i]       * wv;
        a1 += s_ln[128 + i] * wv;
        a2 += s_ln[256 + i] * wv;
    }
    const float sc = 0.08838834764831843f;  // 1/sqrt(128)
    float bqv = bq[t];
    g_q[b*384 + t]       = (a0 + bqv) * sc;
    g_q[b*384 + 128 + t] = (a1 + bqv) * sc;
    g_q[b*384 + 256 + t] = (a2 + bqv) * sc;
}

// ============================================================
// attn_tile: logits + softmax-over-slots + partial updates.
// grid = BB*NTILES, 256 threads. k/v read directly from global.
// ============================================================
__global__ __launch_bounds__(256) void attn_tile(float* __restrict__ out_attn)
{
    __shared__ float attn_s[3*TILE_N];
    __shared__ float red[384];

    const int t = threadIdx.x;
    const int lane = t & 31;
    const int warp = t >> 5;
    const int b    = blockIdx.x >> 3;
    const int tile = blockIdx.x & 7;
    const int n0   = tile * TILE_N;

    // q as float4 per lane
    float4 qf[3];
    #pragma unroll
    for (int kk = 0; kk < 3; kk++)
        qf[kk] = *reinterpret_cast<const float4*>(&g_q[b*384 + kk*128 + lane*4]);

    const float* kb = g_k + ((size_t)b * NN + n0) * HH;

    // each warp handles 16 rows
    #pragma unroll 4
    for (int s = 0; s < 16; s++) {
        int nl = warp*16 + s;
        float4 kv = *reinterpret_cast<const float4*>(kb + (size_t)nl*HH + lane*4);
        float p0 = kv.x*qf[0].x + kv.y*qf[0].y + kv.z*qf[0].z + kv.w*qf[0].w;
        float p1 = kv.x*qf[1].x + kv.y*qf[1].y + kv.z*qf[1].z + kv.w*qf[1].w;
        float p2 = kv.x*qf[2].x + kv.y*qf[2].y + kv.z*qf[2].z + kv.w*qf[2].w;
        #pragma unroll
        for (int off = 16; off >= 1; off >>= 1) {
            p0 += __shfl_xor_sync(0xffffffffu, p0, off);
            p1 += __shfl_xor_sync(0xffffffffu, p1, off);
            p2 += __shfl_xor_sync(0xffffffffu, p2, off);
        }
        if (lane == 0) {
            float mx = fmaxf(p0, fmaxf(p1, p2));
            float e0 = expf(p0 - mx), e1 = expf(p1 - mx), e2 = expf(p2 - mx);
            float inv = 1.0f / (e0 + e1 + e2);
            attn_s[nl]             = e0*inv;
            attn_s[TILE_N + nl]    = e1*inv;
            attn_s[2*TILE_N + nl]  = e2*inv;
        }
    }
    __syncthreads();

    // coalesced attn writeout
    for (int idx = t; idx < 3*TILE_N; idx += 256) {
        int kk = idx >> 7;
        int n  = idx & 127;
        out_attn[b*KK*NN + kk*NN + n0 + n] = attn_s[idx];
    }

    // partial updates: thread owns (d, half); sums 64 rows
    const int d    = t & 127;
    const int half = t >> 7;
    float u0 = 0.f, u1 = 0.f, u2 = 0.f;
    const float* vb = g_v + ((size_t)b*NN + n0 + half*64) * HH + d;
    #pragma unroll 4
    for (int n = 0; n < 64; n++) {
        float vv = vb[(size_t)n*HH];
        int na = half*64 + n;
        u0 += attn_s[na]            * vv;
        u1 += attn_s[TILE_N + na]   * vv;
        u2 += attn_s[2*TILE_N + na] * vv;
    }
    if (half == 1) {
        red[d] = u0; red[128+d] = u1; red[256+d] = u2;
    }
    __syncthreads();
    if (half == 0) {
        float* dst = g_updp + ((size_t)(b*NTILES + tile))*384;
        dst[d]       = u0 + red[d];
        dst[128 + d] = u1 + red[128+d];
        dst[256 + d] = u2 + red[256+d];
    }
}

// ============================================================
// slot_update: reduce partials, GRU, LN, MLP. grid=BB, 256 threads.
// ============================================================
__global__ __launch_bounds__(256) void slot_update(
    const float* __restrict__ Wih, const float* __restrict__ bih,
    const float* __restrict__ Whh, const float* __restrict__ bhh,
    const float* __restrict__ g_m, const float* __restrict__ b_m,
    const float* __restrict__ W1,  const float* __restrict__ b1,
    const float* __restrict__ W2,  const float* __restrict__ b2,
    float* __restrict__ out_slots)
{
    __shared__ float h_prev[384];
    __shared__ float updf[384];
    __shared__ float gi_s[1152];
    __shared__ float gh_s[1152];
    __shared__ float snew[384];
    __shared__ float hm[384];
    __shared__ float a1_s[768];

    const int t = threadIdx.x;
    const int lane = t & 31;
    const int warp = t >> 5;
    const int b = blockIdx.x;

    for (int i = t; i < 384; i += 256) h_prev[i] = g_slots[b*384 + i];
    // reduce partial updates over 8 tiles
    if (t < 128) {
        #pragma unroll
        for (int kk = 0; kk < 3; kk++) {
            float s = 0.0f;
            const float* src = g_updp + (size_t)b*NTILES*384 + kk*128 + t;
            #pragma unroll
            for (int tl = 0; tl < NTILES; tl++) s += src[tl*384];
            updf[kk*128 + t] = s;
        }
    }
    __syncthreads();

    // GRU gate GEMMs
    for (int jj = t; jj < 384; jj += 256) {
        float ai0=0.f, ai1=0.f, ai2=0.f, ah0=0.f, ah1=0.f, ah2=0.f;
        const float* wi = Wih + jj*128;
        const float* wh = Whh + jj*128;
        #pragma unroll 4
        for (int i = 0; i < 128; i++) {
            float wiv = wi[i], whv = wh[i];
            ai0 += updf[i]        * wiv;
            ai1 += updf[128 + i]  * wiv;
            ai2 += updf[256 + i]  * wiv;
            ah0 += h_prev[i]       * whv;
            ah1 += h_prev[128 + i] * whv;
            ah2 += h_prev[256 + i] * whv;
        }
        float bi = bih[jj], bh = bhh[jj];
        gi_s[jj]        = ai0 + bi;
        gi_s[384 + jj]  = ai1 + bi;
        gi_s[768 + jj]  = ai2 + bi;
        gh_s[jj]        = ah0 + bh;
        gh_s[384 + jj]  = ah1 + bh;
        gh_s[768 + jj]  = ah2 + bh;
    }
    __syncthreads();

    // gate combine
    if (t < 128) {
        #pragma unroll
        for (int kk = 0; kk < 3; kk++) {
            float ir  = gi_s[kk*384 + t];
            float iz  = gi_s[kk*384 + 128 + t];
            float inn = gi_s[kk*384 + 256 + t];
            float hr  = gh_s[kk*384 + t];
            float hz  = gh_s[kk*384 + 128 + t];
            float hn  = gh_s[kk*384 + 256 + t];
            float r = 1.0f / (1.0f + expf(-(ir + hr)));
            float z = 1.0f / (1.0f + expf(-(iz + hz)));
            float nn = tanhf(inn + r*hn);
            snew[kk*128 + t] = (1.0f - z)*nn + z*h_prev[kk*128 + t];
        }
    }
    __syncthreads();

    // hm = LN(snew)*g_m + b_m
    if (warp < KK) {
        float x[4];
        float s = 0.0f, sq = 0.0f;
        #pragma unroll
        for (int m = 0; m < 4; m++) {
            x[m] = snew[warp*128 + lane + 32*m];
            s += x[m]; sq += x[m]*x[m];
        }
        #pragma unroll
        for (int off = 16; off >= 1; off >>= 1) {
            s  += __shfl_xor_sync(0xffffffffu, s,  off);
            sq += __shfl_xor_sync(0xffffffffu, sq, off);
        }
        float mu   = s  * (1.0f/128.0f);
        float var  = sq * (1.0f/128.0f) - mu*mu;
        float rstd = rsqrtf(var + 1e-5f);
        #pragma unroll
        for (int m = 0; m < 4; m++) {
            int c = lane + 32*m;
            hm[warp*128 + c] = (x[m]-mu)*rstd*g_m[c] + b_m[c];
        }
    }
    __syncthreads();

    // a1 = gelu_exact(hm @ W1^T + b1)
    {
        float a0 = 0.f, a1v = 0.f, a2 = 0.f;
        const float* w = W1 + t*128;
        #pragma unroll 4
        for (int i = 0; i < 128; i++) {
            float wv = w[i];
            a0  += hm[i]       * wv;
            a1v += hm[128 + i] * wv;
            a2  += hm[256 + i] * wv;
        }
        float bb = b1[t];
        float x0 = a0 + bb, x1 = a1v + bb, x2 = a2 + bb;
        const float is2 = 0.70710678118654752f;
        a1_s[t]        = 0.5f * x0 * (1.0f + erff(x0 * is2));
        a1_s[256 + t]  = 0.5f * x1 * (1.0f + erff(x1 * is2));
        a1_s[512 + t]  = 0.5f * x2 * (1.0f + erff(x2 * is2));
    }
    __syncthreads();

    // slots_out = snew + a1 @ W2^T + b2
    if (t < 128) {
        float a0 = 0.f, a1v = 0.f, a2 = 0.f;
        const float* w = W2 + t*256;
        #pragma unroll 4
        for (int i = 0; i < 256; i++) {
            float wv = w[i];
            a0  += a1_s[i]       * wv;
            a1v += a1_s[256 + i] * wv;
            a2  += a1_s[512 + i] * wv;
        }
        float bb = b2[t];
        int base = b*384;
        float f0 = snew[t]       + a0  + bb;
        float f1 = snew[128 + t] + a1v + bb;
        float f2 = snew[256 + t] + a2  + bb;
        g_slots[base + t]       = f0;  out_slots[base + t]       = f0;
        g_slots[base + 128 + t] = f1;  out_slots[base + 128 + t] = f1;
        g_slots[base + 256 + t] = f2;  out_slots[base + 256 + t] = f2;
    }
}

// ============================================================
extern "C" void kernel_launch(void* const* d_in, const int* in_sizes, int n_in,
                              void* d_out, int out_size)
{
    const float* patch   = (const float*)d_in[0];
    const float* noise   = (const float*)d_in[1];
    const float* slot_mu = (const float*)d_in[2];
    const float* slot_ls = (const float*)d_in[3];
    const float* Wp  = (const float*)d_in[4];
    const float* bp  = (const float*)d_in[5];
    const float* g_in= (const float*)d_in[6];
    const float* b_in= (const float*)d_in[7];
    const float* Wq  = (const float*)d_in[8];
    const float* bq  = (const float*)d_in[9];
    const float* Wk  = (const float*)d_in[10];
    const float* bk  = (const float*)d_in[11];
    const float* Wv  = (const float*)d_in[12];
    const float* bv  = (const float*)d_in[13];
    const float* Wih = (const float*)d_in[14];
    const float* bih = (const float*)d_in[15];
    const float* Whh = (const float*)d_in[16];
    const float* bhh = (const float*)d_in[17];
    const float* g_s = (const float*)d_in[18];
    const float* b_s = (const float*)d_in[19];
    const float* W1  = (const float*)d_in[20];
    const float* b1  = (const float*)d_in[21];
    const float* W2  = (const float*)d_in[22];
    const float* b2  = (const float*)d_in[23];
    const float* g_m = (const float*)d_in[24];
    const float* b_m = (const float*)d_in[25];

    float* out       = (float*)d_out;
    float* out_slots = out;                     // B*K*H = 49152
    float* out_attn  = out + BB*KK*HH;          // B*K*N = 393216

    const size_t SM1 = SM1_FLOATS * sizeof(float);   // 136 KB
    cudaFuncSetAttribute(fused_proj_ln_kv, cudaFuncAttributeMaxDynamicSharedMemorySize, (int)SM1);

    fused_proj_ln_kv<<<(BB*NN)/BM, 256, SM1>>>(patch, Wp, bp, g_in, b_in, Wk, bk, Wv, bv);
    init_slots<<<(BB*KK*HH + 255)/256, 256>>>(noise, slot_mu, slot_ls);
    for (int it = 0; it < 3; it++) {
        compute_q<<<BB, 128>>>(Wq, bq, g_s, b_s);
        attn_tile<<<BB*NTILES, 256>>>(out_attn);
        slot_update<<<BB, 256>>>(Wih, bih, Whh, bhh, g_m, b_m,
                                 W1, b1, W2, b2, out_slots);
    }
}

// round 9
// speedup vs baseline: 2.2593x; 1.5791x over previous
#include <cuda_runtime.h>
#include <cuda_bf16.h>
#include <math.h>

#define BB   128
#define NN   1024
#define DIN  192
#define HH   128
#define KK   3
#define NTILES 8
#define TILE_N 128

typedef unsigned int u32;

// -------- device scratch (no allocations allowed) --------
__device__ float g_inputs[(size_t)BB*NN*HH];   // 64 MB, LN'ed projected inputs
__device__ float g_slots[BB*KK*HH];
__device__ float g_qk[BB*KK*HH];               // q' = Wk^T (scale*q)
__device__ float g_qbk[BB*4];                  // (scale*q) . bk per slot
__device__ float g_updp[BB*NTILES*KK*HH];      // partial attn.inputs
__device__ float g_updsum[BB*NTILES*4];        // partial attn row sums

// bf16 split helpers
__device__ __forceinline__ void bsplit(float x, float& h, float& r) {
    __nv_bfloat16 b = __float2bfloat16_rn(x);
    h = __bfloat162float(b);
    r = x - h;
}
__device__ __forceinline__ u32 pk2(float lo, float hi) {
    __nv_bfloat162 t = __floats2bfloat162_rn(lo, hi);
    return *reinterpret_cast<u32*>(&t);
}

__device__ __forceinline__ void mma16816(float* c, u32 a0, u32 a1, u32 a2, u32 a3,
                                         u32 b0, u32 b1) {
    asm volatile(
        "mma.sync.aligned.m16n8k16.row.col.f32.bf16.bf16.f32 "
        "{%0,%1,%2,%3}, {%4,%5,%6,%7}, {%8,%9}, {%0,%1,%2,%3};"
        : "+f"(c[0]), "+f"(c[1]), "+f"(c[2]), "+f"(c[3])
        : "r"(a0), "r"(a1), "r"(a2), "r"(a3), "r"(b0), "r"(b1));
}

// ============================================================
// Kernel 1: inputs = LN(patch @ Wp^T + bp) via bf16x3 mma.sync.
// 128 rows/CTA, 1024 CTAs, 256 threads (8 warps, 16 rows each).
// ============================================================
#define RSTRIDE 400                      // bytes per 192-col bf16 row (padded)
#define AH_OFF  0
#define AL_OFF  (128*RSTRIDE)            // 51200
#define WH_OFF  (2*128*RSTRIDE)          // 102400
#define WL_OFF  (3*128*RSTRIDE)          // 153600
#define PAR_OFF (4*128*RSTRIDE)          // 204800
#define SM1_BYTES (PAR_OFF + 3*128*4)    // 206336

__global__ __launch_bounds__(256) void proj_ln(
    const float* __restrict__ patch,
    const float* __restrict__ Wp, const float* __restrict__ bp,
    const float* __restrict__ g_in, const float* __restrict__ b_in)
{
    extern __shared__ char smc[];
    float* bpS = reinterpret_cast<float*>(smc + PAR_OFF);
    float* gS  = bpS + 128;
    float* bS  = gS + 128;

    const int t    = threadIdx.x;
    const int warp = t >> 5;
    const int lane = t & 31;
    const int g    = lane >> 2;
    const int tig  = lane & 3;
    const long rowbase = (long)blockIdx.x * 128;

    if (t < 128) { bpS[t] = bp[t]; gS[t] = g_in[t]; bS[t] = b_in[t]; }

    // convert patch tile -> Ah/Al (bf16 hi/lo, padded rows)
    for (int idx = t; idx < 128*48; idx += 256) {
        int row = idx / 48;
        int c4  = idx % 48;
        float4 gv = *reinterpret_cast<const float4*>(patch + (rowbase + row)*DIN + c4*4);
        float h0,h1,h2,h3,r0,r1,r2,r3;
        bsplit(gv.x,h0,r0); bsplit(gv.y,h1,r1); bsplit(gv.z,h2,r2); bsplit(gv.w,h3,r3);
        int off = row*RSTRIDE + c4*8;
        *reinterpret_cast<uint2*>(smc + AH_OFF + off) = make_uint2(pk2(h0,h1), pk2(h2,h3));
        *reinterpret_cast<uint2*>(smc + AL_OFF + off) = make_uint2(pk2(r0,r1), pk2(r2,r3));
    }
    // convert Wp -> Wh/Wl
    for (int idx = t; idx < 128*48; idx += 256) {
        int row = idx / 48;
        int c4  = idx % 48;
        float4 gv = *reinterpret_cast<const float4*>(Wp + row*DIN + c4*4);
        float h0,h1,h2,h3,r0,r1,r2,r3;
        bsplit(gv.x,h0,r0); bsplit(gv.y,h1,r1); bsplit(gv.z,h2,r2); bsplit(gv.w,h3,r3);
        int off = row*RSTRIDE + c4*8;
        *reinterpret_cast<uint2*>(smc + WH_OFF + off) = make_uint2(pk2(h0,h1), pk2(h2,h3));
        *reinterpret_cast<uint2*>(smc + WL_OFF + off) = make_uint2(pk2(r0,r1), pk2(r2,r3));
    }
    __syncthreads();

    float acc[16][4];
    #pragma unroll
    for (int nf = 0; nf < 16; nf++)
        #pragma unroll
        for (int i = 0; i < 4; i++) acc[nf][i] = 0.0f;

    const int r0 = 16*warp + g;
    const int aoff0 = r0 * RSTRIDE + tig * 4;

    // 3 passes: Ah*Wh, Al*Wh, Ah*Wl
    #pragma unroll
    for (int pass = 0; pass < 3; pass++) {
        const char* A = smc + (pass == 1 ? AL_OFF : AH_OFF);
        const char* B = smc + (pass == 2 ? WL_OFF : WH_OFF);
        #pragma unroll
        for (int ks = 0; ks < 12; ks++) {
            int ao = aoff0 + ks*32;
            u32 a0 = *reinterpret_cast<const u32*>(A + ao);
            u32 a1 = *reinterpret_cast<const u32*>(A + ao + 8*RSTRIDE);
            u32 a2 = *reinterpret_cast<const u32*>(A + ao + 16);
            u32 a3 = *reinterpret_cast<const u32*>(A + ao + 8*RSTRIDE + 16);
            #pragma unroll
            for (int nf = 0; nf < 16; nf++) {
                int bo = (8*nf + g)*RSTRIDE + ks*32 + tig*4;
                u32 b0 = *reinterpret_cast<const u32*>(B + bo);
                u32 b1 = *reinterpret_cast<const u32*>(B + bo + 16);
                mma16816(acc[nf], a0, a1, a2, a3, b0, b1);
            }
        }
    }

    // ---- epilogue: +bias, LayerNorm over quad, store inputs ----
    #pragma unroll
    for (int nf = 0; nf < 16; nf++) {
        int c = 8*nf + 2*tig;
        acc[nf][0] += bpS[c];   acc[nf][1] += bpS[c+1];
        acc[nf][2] += bpS[c];   acc[nf][3] += bpS[c+1];
    }
    float s0 = 0.f, q0 = 0.f, s1 = 0.f, q1 = 0.f;
    #pragma unroll
    for (int nf = 0; nf < 16; nf++) {
        s0 += acc[nf][0] + acc[nf][1];
        q0 += acc[nf][0]*acc[nf][0] + acc[nf][1]*acc[nf][1];
        s1 += acc[nf][2] + acc[nf][3];
        q1 += acc[nf][2]*acc[nf][2] + acc[nf][3]*acc[nf][3];
    }
    #pragma unroll
    for (int m = 1; m <= 2; m <<= 1) {
        s0 += __shfl_xor_sync(0xffffffffu, s0, m);
        q0 += __shfl_xor_sync(0xffffffffu, q0, m);
        s1 += __shfl_xor_sync(0xffffffffu, s1, m);
        q1 += __shfl_xor_sync(0xffffffffu, q1, m);
    }
    float mu0 = s0*(1.0f/128.0f), var0 = q0*(1.0f/128.0f) - mu0*mu0;
    float mu1 = s1*(1.0f/128.0f), var1 = q1*(1.0f/128.0f) - mu1*mu1;
    float rs0 = rsqrtf(var0 + 1e-5f);
    float rs1 = rsqrtf(var1 + 1e-5f);

    float* out0 = g_inputs + (rowbase + r0) * HH;
    float* out1 = g_inputs + (rowbase + r0 + 8) * HH;
    #pragma unroll
    for (int nf = 0; nf < 16; nf++) {
        int c = 8*nf + 2*tig;
        float2 y0 = make_float2((acc[nf][0]-mu0)*rs0*gS[c]   + bS[c],
                                (acc[nf][1]-mu0)*rs0*gS[c+1] + bS[c+1]);
        float2 y1 = make_float2((acc[nf][2]-mu1)*rs1*gS[c]   + bS[c],
                                (acc[nf][3]-mu1)*rs1*gS[c+1] + bS[c+1]);
        *reinterpret_cast<float2*>(out0 + c) = y0;
        *reinterpret_cast<float2*>(out1 + c) = y1;
    }
}

// ============================================================
// init_slots
// ============================================================
__global__ void init_slots(const float* __restrict__ noise,
                           const float* __restrict__ mu,
                           const float* __restrict__ ls)
{
    int i = blockIdx.x * 256 + threadIdx.x;
    if (i < BB*KK*HH) {
        int r = i % (KK*HH);
        g_slots[i] = mu[r] + expf(ls[r]) * noise[i];
    }
}

// ============================================================
// compute_q: qs = scale*(LN(slots)@Wq^T + bq); q' = Wk^T qs; qbk = qs.bk
// grid=BB, 128 threads.
// ============================================================
__global__ __launch_bounds__(128) void compute_q(
    const float* __restrict__ Wq,  const float* __restrict__ bq,
    const float* __restrict__ Wk,  const float* __restrict__ bk,
    const float* __restrict__ g_s, const float* __restrict__ b_s)
{
    __shared__ float h[384];
    __shared__ float s_ln[384];
    __shared__ float qs[384];
    __shared__ float pr[384];
    const int t = threadIdx.x;
    const int lane = t & 31;
    const int warp = t >> 5;
    const int b = blockIdx.x;

    for (int i = t; i < 384; i += 128) h[i] = g_slots[b*384 + i];
    __syncthreads();

    if (warp < KK) {
        float x[4];
        float s = 0.0f, sq = 0.0f;
        #pragma unroll
        for (int m = 0; m < 4; m++) {
            x[m] = h[warp*128 + lane + 32*m];
            s += x[m]; sq += x[m]*x[m];
        }
        #pragma unroll
        for (int off = 16; off >= 1; off >>= 1) {
            s  += __shfl_xor_sync(0xffffffffu, s,  off);
            sq += __shfl_xor_sync(0xffffffffu, sq, off);
        }
        float mu   = s  * (1.0f/128.0f);
        float var  = sq * (1.0f/128.0f) - mu*mu;
        float rstd = rsqrtf(var + 1e-5f);
        #pragma unroll
        for (int m = 0; m < 4; m++) {
            int c = lane + 32*m;
            s_ln[warp*128 + c] = (x[m]-mu)*rstd*g_s[c] + b_s[c];
        }
    }
    __syncthreads();

    {
        float a0 = 0.f, a1 = 0.f, a2 = 0.f;
        const float* w = Wq + t*128;
        #pragma unroll 4
        for (int i = 0; i < 128; i++) {
            float wv = w[i];
            a0 += s_ln[i]       * wv;
            a1 += s_ln[128 + i] * wv;
            a2 += s_ln[256 + i] * wv;
        }
        const float sc = 0.08838834764831843f;  // 1/sqrt(128)
        float bqv = bq[t];
        qs[t]       = (a0 + bqv) * sc;
        qs[128 + t] = (a1 + bqv) * sc;
        qs[256 + t] = (a2 + bqv) * sc;
    }
    __syncthreads();

    // q'[s][t] = sum_j qs[s][j] * Wk[j][t]   (coalesced over t)
    {
        float a0 = 0.f, a1 = 0.f, a2 = 0.f;
        #pragma unroll 4
        for (int j = 0; j < 128; j++) {
            float wv = Wk[j*128 + t];
            a0 += qs[j]       * wv;
            a1 += qs[128 + j] * wv;
            a2 += qs[256 + j] * wv;
        }
        g_qk[b*384 + t]       = a0;
        g_qk[b*384 + 128 + t] = a1;
        g_qk[b*384 + 256 + t] = a2;
    }

    // qbk[s] = qs[s] . bk
    {
        float bkt = bk[t];
        pr[t]       = qs[t]       * bkt;
        pr[128 + t] = qs[128 + t] * bkt;
        pr[256 + t] = qs[256 + t] * bkt;
    }
    __syncthreads();
    if (t < KK) {
        float s = 0.0f;
        #pragma unroll 4
        for (int i = 0; i < 128; i++) s += pr[t*128 + i];
        g_qbk[b*4 + t] = s;
    }
}

// ============================================================
// attn_tile: logits on inputs + softmax-over-slots + partial (attn.inputs, rowsum)
// grid = BB*NTILES, 256 threads.
// ============================================================
__global__ __launch_bounds__(256) void attn_tile(float* __restrict__ out_attn)
{
    __shared__ float attn_s[3*TILE_N];
    __shared__ float red[384];
    __shared__ float red2[8];

    const int t = threadIdx.x;
    const int lane = t & 31;
    const int warp = t >> 5;
    const int b    = blockIdx.x >> 3;
    const int tile = blockIdx.x & 7;
    const int n0   = tile * TILE_N;

    float4 qf[3];
    #pragma unroll
    for (int kk = 0; kk < 3; kk++)
        qf[kk] = *reinterpret_cast<const float4*>(&g_qk[b*384 + kk*128 + lane*4]);
    float qb0 = g_qbk[b*4 + 0];
    float qb1 = g_qbk[b*4 + 1];
    float qb2 = g_qbk[b*4 + 2];

    const float* ib = g_inputs + ((size_t)b * NN + n0) * HH;

    #pragma unroll 4
    for (int s = 0; s < 16; s++) {
        int nl = warp*16 + s;
        float4 kv = *reinterpret_cast<const float4*>(ib + (size_t)nl*HH + lane*4);
        float p0 = kv.x*qf[0].x + kv.y*qf[0].y + kv.z*qf[0].z + kv.w*qf[0].w;
        float p1 = kv.x*qf[1].x + kv.y*qf[1].y + kv.z*qf[1].z + kv.w*qf[1].w;
        float p2 = kv.x*qf[2].x + kv.y*qf[2].y + kv.z*qf[2].z + kv.w*qf[2].w;
        #pragma unroll
        for (int off = 16; off >= 1; off >>= 1) {
            p0 += __shfl_xor_sync(0xffffffffu, p0, off);
            p1 += __shfl_xor_sync(0xffffffffu, p1, off);
            p2 += __shfl_xor_sync(0xffffffffu, p2, off);
        }
        if (lane == 0) {
            p0 += qb0; p1 += qb1; p2 += qb2;
            float mx = fmaxf(p0, fmaxf(p1, p2));
            float e0 = expf(p0 - mx), e1 = expf(p1 - mx), e2 = expf(p2 - mx);
            float inv = 1.0f / (e0 + e1 + e2);
            attn_s[nl]             = e0*inv;
            attn_s[TILE_N + nl]    = e1*inv;
            attn_s[2*TILE_N + nl]  = e2*inv;
        }
    }
    __syncthreads();

    // coalesced attn writeout
    for (int idx = t; idx < 3*TILE_N; idx += 256) {
        int kk = idx >> 7;
        int n  = idx & 127;
        out_attn[b*KK*NN + kk*NN + n0 + n] = attn_s[idx];
    }

    // partial attn.inputs + rowsums; thread owns (d, half), sums 64 rows
    const int d    = t & 127;
    const int half = t >> 7;
    float u0 = 0.f, u1 = 0.f, u2 = 0.f;
    float as0 = 0.f, as1 = 0.f, as2 = 0.f;
    const float* vb = ib + (size_t)(half*64) * HH + d;
    #pragma unroll 4
    for (int n = 0; n < 64; n++) {
        float vv = vb[(size_t)n*HH];
        int na = half*64 + n;
        float a0 = attn_s[na];
        float a1 = attn_s[TILE_N + na];
        float a2 = attn_s[2*TILE_N + na];
        u0 += a0 * vv;  u1 += a1 * vv;  u2 += a2 * vv;
        as0 += a0; as1 += a1; as2 += a2;
    }
    if (half == 1) {
        red[d] = u0; red[128+d] = u1; red[256+d] = u2;
        if (d == 0) { red2[0] = as0; red2[1] = as1; red2[2] = as2; }
    }
    __syncthreads();
    if (half == 0) {
        float* dst = g_updp + ((size_t)(b*NTILES + tile))*384;
        dst[d]       = u0 + red[d];
        dst[128 + d] = u1 + red[128+d];
        dst[256 + d] = u2 + red[256+d];
        if (d == 0) {
            float* ds = g_updsum + (size_t)(b*NTILES + tile)*4;
            ds[0] = as0 + red2[0];
            ds[1] = as1 + red2[1];
            ds[2] = as2 + red2[2];
        }
    }
}

// ============================================================
// slot_update: reduce partials, apply Wv/bv, GRU, LN, MLP. grid=BB, 256 thr.
// ============================================================
__global__ __launch_bounds__(256) void slot_update(
    const float* __restrict__ Wv,  const float* __restrict__ bv,
    const float* __restrict__ Wih, const float* __restrict__ bih,
    const float* __restrict__ Whh, const float* __restrict__ bhh,
    const float* __restrict__ g_m, const float* __restrict__ b_m,
    const float* __restrict__ W1,  const float* __restrict__ b1,
    const float* __restrict__ W2,  const float* __restrict__ b2,
    float* __restrict__ out_slots)
{
    __shared__ float h_prev[384];
    __shared__ float ared[384];
    __shared__ float asum[4];
    __shared__ float updf[384];
    __shared__ float gi_s[1152];
    __shared__ float gh_s[1152];
    __shared__ float snew[384];
    __shared__ float hm[384];
    __shared__ float a1_s[768];

    const int t = threadIdx.x;
    const int lane = t & 31;
    const int warp = t >> 5;
    const int b = blockIdx.x;

    for (int i = t; i < 384; i += 256) h_prev[i] = g_slots[b*384 + i];
    if (t < 128) {
        #pragma unroll
        for (int kk = 0; kk < 3; kk++) {
            float s = 0.0f;
            const float* src = g_updp + (size_t)b*NTILES*384 + kk*128 + t;
            #pragma unroll
            for (int tl = 0; tl < NTILES; tl++) s += src[tl*384];
            ared[kk*128 + t] = s;
        }
    } else if (t < 131) {
        int s = t - 128;
        float acc = 0.0f;
        #pragma unroll
        for (int tl = 0; tl < NTILES; tl++) acc += g_updsum[(size_t)(b*NTILES + tl)*4 + s];
        asum[s] = acc;
    }
    __syncthreads();

    // updates = ared @ Wv^T + asum*bv
    if (t < 128) {
        float u0 = 0.f, u1 = 0.f, u2 = 0.f;
        const float* w = Wv + t*128;
        #pragma unroll 4
        for (int i = 0; i < 128; i++) {
            float wv = w[i];
            u0 += ared[i]       * wv;
            u1 += ared[128 + i] * wv;
            u2 += ared[256 + i] * wv;
        }
        float bvt = bv[t];
        updf[t]       = u0 + asum[0]*bvt;
        updf[128 + t] = u1 + asum[1]*bvt;
        updf[256 + t] = u2 + asum[2]*bvt;
    }
    __syncthreads();

    // GRU gate GEMMs
    for (int jj = t; jj < 384; jj += 256) {
        float ai0=0.f, ai1=0.f, ai2=0.f, ah0=0.f, ah1=0.f, ah2=0.f;
        const float* wi = Wih + jj*128;
        const float* wh = Whh + jj*128;
        #pragma unroll 4
        for (int i = 0; i < 128; i++) {
            float wiv = wi[i], whv = wh[i];
            ai0 += updf[i]        * wiv;
            ai1 += updf[128 + i]  * wiv;
            ai2 += updf[256 + i]  * wiv;
            ah0 += h_prev[i]       * whv;
            ah1 += h_prev[128 + i] * whv;
            ah2 += h_prev[256 + i] * whv;
        }
        float bi = bih[jj], bh = bhh[jj];
        gi_s[jj]        = ai0 + bi;
        gi_s[384 + jj]  = ai1 + bi;
        gi_s[768 + jj]  = ai2 + bi;
        gh_s[jj]        = ah0 + bh;
        gh_s[384 + jj]  = ah1 + bh;
        gh_s[768 + jj]  = ah2 + bh;
    }
    __syncthreads();

    if (t < 128) {
        #pragma unroll
        for (int kk = 0; kk < 3; kk++) {
            float ir  = gi_s[kk*384 + t];
            float iz  = gi_s[kk*384 + 128 + t];
            float inn = gi_s[kk*384 + 256 + t];
            float hr  = gh_s[kk*384 + t];
            float hz  = gh_s[kk*384 + 128 + t];
            float hn  = gh_s[kk*384 + 256 + t];
            float r = 1.0f / (1.0f + expf(-(ir + hr)));
            float z = 1.0f / (1.0f + expf(-(iz + hz)));
            float nn = tanhf(inn + r*hn);
            snew[kk*128 + t] = (1.0f - z)*nn + z*h_prev[kk*128 + t];
        }
    }
    __syncthreads();

    if (warp < KK) {
        float x[4];
        float s = 0.0f, sq = 0.0f;
        #pragma unroll
        for (int m = 0; m < 4; m++) {
            x[m] = snew[warp*128 + lane + 32*m];
            s += x[m]; sq += x[m]*x[m];
        }
        #pragma unroll
        for (int off = 16; off >= 1; off >>= 1) {
            s  += __shfl_xor_sync(0xffffffffu, s,  off);
            sq += __shfl_xor_sync(0xffffffffu, sq, off);
        }
        float mu   = s  * (1.0f/128.0f);
        float var  = sq * (1.0f/128.0f) - mu*mu;
        float rstd = rsqrtf(var + 1e-5f);
        #pragma unroll
        for (int m = 0; m < 4; m++) {
            int c = lane + 32*m;
            hm[warp*128 + c] = (x[m]-mu)*rstd*g_m[c] + b_m[c];
        }
    }
    __syncthreads();

    {
        float a0 = 0.f, a1v = 0.f, a2 = 0.f;
        const float* w = W1 + t*128;
        #pragma unroll 4
        for (int i = 0; i < 128; i++) {
            float wv = w[i];
            a0  += hm[i]       * wv;
            a1v += hm[128 + i] * wv;
            a2  += hm[256 + i] * wv;
        }
        float bb = b1[t];
        float x0 = a0 + bb, x1 = a1v + bb, x2 = a2 + bb;
        const float is2 = 0.70710678118654752f;
        a1_s[t]        = 0.5f * x0 * (1.0f + erff(x0 * is2));
        a1_s[256 + t]  = 0.5f * x1 * (1.0f + erff(x1 * is2));
        a1_s[512 + t]  = 0.5f * x2 * (1.0f + erff(x2 * is2));
    }
    __syncthreads();

    if (t < 128) {
        float a0 = 0.f, a1v = 0.f, a2 = 0.f;
        const float* w = W2 + t*256;
        #pragma unroll 4
        for (int i = 0; i < 256; i++) {
            float wv = w[i];
            a0  += a1_s[i]       * wv;
            a1v += a1_s[256 + i] * wv;
            a2  += a1_s[512 + i] * wv;
        }
        float bb = b2[t];
        int base = b*384;
        float f0 = snew[t]       + a0  + bb;
        float f1 = snew[128 + t] + a1v + bb;
        float f2 = snew[256 + t] + a2  + bb;
        g_slots[base + t]       = f0;  out_slots[base + t]       = f0;
        g_slots[base + 128 + t] = f1;  out_slots[base + 128 + t] = f1;
        g_slots[base + 256 + t] = f2;  out_slots[base + 256 + t] = f2;
    }
}

// ============================================================
extern "C" void kernel_launch(void* const* d_in, const int* in_sizes, int n_in,
                              void* d_out, int out_size)
{
    const float* patch   = (const float*)d_in[0];
    const float* noise   = (const float*)d_in[1];
    const float* slot_mu = (const float*)d_in[2];
    const float* slot_ls = (const float*)d_in[3];
    const float* Wp  = (const float*)d_in[4];
    const float* bp  = (const float*)d_in[5];
    const float* g_in= (const float*)d_in[6];
    const float* b_in= (const float*)d_in[7];
    const float* Wq  = (const float*)d_in[8];
    const float* bq  = (const float*)d_in[9];
    const float* Wk  = (const float*)d_in[10];
    const float* bk  = (const float*)d_in[11];
    const float* Wv  = (const float*)d_in[12];
    const float* bv  = (const float*)d_in[13];
    const float* Wih = (const float*)d_in[14];
    const float* bih = (const float*)d_in[15];
    const float* Whh = (const float*)d_in[16];
    const float* bhh = (const float*)d_in[17];
    const float* g_s = (const float*)d_in[18];
    const float* b_s = (const float*)d_in[19];
    const float* W1  = (const float*)d_in[20];
    const float* b1  = (const float*)d_in[21];
    const float* W2  = (const float*)d_in[22];
    const float* b2  = (const float*)d_in[23];
    const float* g_m = (const float*)d_in[24];
    const float* b_m = (const float*)d_in[25];

    float* out       = (float*)d_out;
    float* out_slots = out;                     // B*K*H = 49152
    float* out_attn  = out + BB*KK*HH;          // B*K*N = 393216

    cudaFuncSetAttribute(proj_ln, cudaFuncAttributeMaxDynamicSharedMemorySize, SM1_BYTES);

    proj_ln<<<(BB*NN)/128, 256, SM1_BYTES>>>(patch, Wp, bp, g_in, b_in);
    init_slots<<<(BB*KK*HH + 255)/256, 256>>>(noise, slot_mu, slot_ls);
    for (int it = 0; it < 3; it++) {
        compute_q<<<BB, 128>>>(Wq, bq, Wk, bk, g_s, b_s);
        attn_tile<<<BB*NTILES, 256>>>(out_attn);
        slot_update<<<BB, 256>>>(Wv, bv, Wih, bih, Whh, bhh, g_m, b_m,
                                 W1, b1, W2, b2, out_slots);
    }
}

// round 10
// speedup vs baseline: 2.3794x; 1.0532x over previous
#include <cuda_runtime.h>
#include <cuda_bf16.h>
#include <math.h>

#define BB   128
#define NN   1024
#define DIN  192
#define HH   128
#define KK   3
#define NTILES 8
#define TILE_N 128

typedef unsigned int u32;

// -------- device scratch (no allocations allowed) --------
__device__ float g_inputs[(size_t)BB*NN*HH];   // 64 MB, LN'ed projected inputs
__device__ float g_slots[BB*KK*HH];
__device__ float g_qk[BB*KK*HH];               // q' = Wk^T (scale*q)
__device__ float g_qbk[BB*4];                  // (scale*q) . bk per slot
__device__ float g_updp[BB*NTILES*KK*HH];      // partial attn.inputs
__device__ float g_updsum[BB*NTILES*4];        // partial attn row sums

// bf16 split helpers
__device__ __forceinline__ void bsplit(float x, float& h, float& r) {
    __nv_bfloat16 b = __float2bfloat16_rn(x);
    h = __bfloat162float(b);
    r = x - h;
}
__device__ __forceinline__ u32 pk2(float lo, float hi) {
    __nv_bfloat162 t = __floats2bfloat162_rn(lo, hi);
    return *reinterpret_cast<u32*>(&t);
}

__device__ __forceinline__ void mma16816(float* c, u32 a0, u32 a1, u32 a2, u32 a3,
                                         u32 b0, u32 b1) {
    asm volatile(
        "mma.sync.aligned.m16n8k16.row.col.f32.bf16.bf16.f32 "
        "{%0,%1,%2,%3}, {%4,%5,%6,%7}, {%8,%9}, {%0,%1,%2,%3};"
        : "+f"(c[0]), "+f"(c[1]), "+f"(c[2]), "+f"(c[3])
        : "r"(a0), "r"(a1), "r"(a2), "r"(a3), "r"(b0), "r"(b1));
}

// ============================================================
// Kernel 1: inputs = LN(patch @ Wp^T + bp) via bf16x3 mma.sync.
// 128 rows/CTA, 1024 CTAs, 256 threads (8 warps, 16 rows each).
// ============================================================
#define RSTRIDE 400
#define AH_OFF  0
#define AL_OFF  (128*RSTRIDE)
#define WH_OFF  (2*128*RSTRIDE)
#define WL_OFF  (3*128*RSTRIDE)
#define PAR_OFF (4*128*RSTRIDE)
#define SM1_BYTES (PAR_OFF + 3*128*4)

__global__ __launch_bounds__(256) void proj_ln(
    const float* __restrict__ patch,
    const float* __restrict__ Wp, const float* __restrict__ bp,
    const float* __restrict__ g_in, const float* __restrict__ b_in)
{
    extern __shared__ char smc[];
    float* bpS = reinterpret_cast<float*>(smc + PAR_OFF);
    float* gS  = bpS + 128;
    float* bS  = gS + 128;

    const int t    = threadIdx.x;
    const int warp = t >> 5;
    const int lane = t & 31;
    const int g    = lane >> 2;
    const int tig  = lane & 3;
    const long rowbase = (long)blockIdx.x * 128;

    if (t < 128) { bpS[t] = bp[t]; gS[t] = g_in[t]; bS[t] = b_in[t]; }

    for (int idx = t; idx < 128*48; idx += 256) {
        int row = idx / 48;
        int c4  = idx % 48;
        float4 gv = *reinterpret_cast<const float4*>(patch + (rowbase + row)*DIN + c4*4);
        float h0,h1,h2,h3,r0,r1,r2,r3;
        bsplit(gv.x,h0,r0); bsplit(gv.y,h1,r1); bsplit(gv.z,h2,r2); bsplit(gv.w,h3,r3);
        int off = row*RSTRIDE + c4*8;
        *reinterpret_cast<uint2*>(smc + AH_OFF + off) = make_uint2(pk2(h0,h1), pk2(h2,h3));
        *reinterpret_cast<uint2*>(smc + AL_OFF + off) = make_uint2(pk2(r0,r1), pk2(r2,r3));
    }
    for (int idx = t; idx < 128*48; idx += 256) {
        int row = idx / 48;
        int c4  = idx % 48;
        float4 gv = *reinterpret_cast<const float4*>(Wp + row*DIN + c4*4);
        float h0,h1,h2,h3,r0,r1,r2,r3;
        bsplit(gv.x,h0,r0); bsplit(gv.y,h1,r1); bsplit(gv.z,h2,r2); bsplit(gv.w,h3,r3);
        int off = row*RSTRIDE + c4*8;
        *reinterpret_cast<uint2*>(smc + WH_OFF + off) = make_uint2(pk2(h0,h1), pk2(h2,h3));
        *reinterpret_cast<uint2*>(smc + WL_OFF + off) = make_uint2(pk2(r0,r1), pk2(r2,r3));
    }
    __syncthreads();

    float acc[16][4];
    #pragma unroll
    for (int nf = 0; nf < 16; nf++)
        #pragma unroll
        for (int i = 0; i < 4; i++) acc[nf][i] = 0.0f;

    const int r0 = 16*warp + g;
    const int aoff0 = r0 * RSTRIDE + tig * 4;

    #pragma unroll
    for (int pass = 0; pass < 3; pass++) {
        const char* A = smc + (pass == 1 ? AL_OFF : AH_OFF);
        const char* B = smc + (pass == 2 ? WL_OFF : WH_OFF);
        #pragma unroll
        for (int ks = 0; ks < 12; ks++) {
            int ao = aoff0 + ks*32;
            u32 a0 = *reinterpret_cast<const u32*>(A + ao);
            u32 a1 = *reinterpret_cast<const u32*>(A + ao + 8*RSTRIDE);
            u32 a2 = *reinterpret_cast<const u32*>(A + ao + 16);
            u32 a3 = *reinterpret_cast<const u32*>(A + ao + 8*RSTRIDE + 16);
            #pragma unroll
            for (int nf = 0; nf < 16; nf++) {
                int bo = (8*nf + g)*RSTRIDE + ks*32 + tig*4;
                u32 b0 = *reinterpret_cast<const u32*>(B + bo);
                u32 b1 = *reinterpret_cast<const u32*>(B + bo + 16);
                mma16816(acc[nf], a0, a1, a2, a3, b0, b1);
            }
        }
    }

    #pragma unroll
    for (int nf = 0; nf < 16; nf++) {
        int c = 8*nf + 2*tig;
        acc[nf][0] += bpS[c];   acc[nf][1] += bpS[c+1];
        acc[nf][2] += bpS[c];   acc[nf][3] += bpS[c+1];
    }
    float s0 = 0.f, q0 = 0.f, s1 = 0.f, q1 = 0.f;
    #pragma unroll
    for (int nf = 0; nf < 16; nf++) {
        s0 += acc[nf][0] + acc[nf][1];
        q0 += acc[nf][0]*acc[nf][0] + acc[nf][1]*acc[nf][1];
        s1 += acc[nf][2] + acc[nf][3];
        q1 += acc[nf][2]*acc[nf][2] + acc[nf][3]*acc[nf][3];
    }
    #pragma unroll
    for (int m = 1; m <= 2; m <<= 1) {
        s0 += __shfl_xor_sync(0xffffffffu, s0, m);
        q0 += __shfl_xor_sync(0xffffffffu, q0, m);
        s1 += __shfl_xor_sync(0xffffffffu, s1, m);
        q1 += __shfl_xor_sync(0xffffffffu, q1, m);
    }
    float mu0 = s0*(1.0f/128.0f), var0 = q0*(1.0f/128.0f) - mu0*mu0;
    float mu1 = s1*(1.0f/128.0f), var1 = q1*(1.0f/128.0f) - mu1*mu1;
    float rs0 = rsqrtf(var0 + 1e-5f);
    float rs1 = rsqrtf(var1 + 1e-5f);

    float* out0 = g_inputs + (rowbase + r0) * HH;
    float* out1 = g_inputs + (rowbase + r0 + 8) * HH;
    #pragma unroll
    for (int nf = 0; nf < 16; nf++) {
        int c = 8*nf + 2*tig;
        float2 y0 = make_float2((acc[nf][0]-mu0)*rs0*gS[c]   + bS[c],
                                (acc[nf][1]-mu0)*rs0*gS[c+1] + bS[c+1]);
        float2 y1 = make_float2((acc[nf][2]-mu1)*rs1*gS[c]   + bS[c],
                                (acc[nf][3]-mu1)*rs1*gS[c+1] + bS[c+1]);
        *reinterpret_cast<float2*>(out0 + c) = y0;
        *reinterpret_cast<float2*>(out1 + c) = y1;
    }
}

// ============================================================
// q computation from slots in smem `h` -> g_qk/g_qbk. 256-thread helper.
// ============================================================
__device__ __forceinline__ void q_from_slots(
    const float* __restrict__ h,      // smem [384]
    float* __restrict__ s_ln, float* __restrict__ qs, float* __restrict__ pr,
    const float* __restrict__ Wq,  const float* __restrict__ bq,
    const float* __restrict__ Wk,  const float* __restrict__ bk,
    const float* __restrict__ g_s, const float* __restrict__ b_s,
    int b, int t)
{
    const int lane = t & 31;
    const int warp = t >> 5;

    if (warp < KK) {
        float x[4];
        float s = 0.0f, sq = 0.0f;
        #pragma unroll
        for (int m = 0; m < 4; m++) {
            x[m] = h[warp*128 + lane + 32*m];
            s += x[m]; sq += x[m]*x[m];
        }
        #pragma unroll
        for (int off = 16; off >= 1; off >>= 1) {
            s  += __shfl_xor_sync(0xffffffffu, s,  off);
            sq += __shfl_xor_sync(0xffffffffu, sq, off);
        }
        float mu   = s  * (1.0f/128.0f);
        float var  = sq * (1.0f/128.0f) - mu*mu;
        float rstd = rsqrtf(var + 1e-5f);
        #pragma unroll
        for (int m = 0; m < 4; m++) {
            int c = lane + 32*m;
            s_ln[warp*128 + c] = (x[m]-mu)*rstd*g_s[c] + b_s[c];
        }
    }
    __syncthreads();

    if (t < 128) {
        float a0 = 0.f, a1 = 0.f, a2 = 0.f;
        const float* w = Wq + t*128;
        #pragma unroll 4
        for (int i = 0; i < 128; i++) {
            float wv = w[i];
            a0 += s_ln[i]       * wv;
            a1 += s_ln[128 + i] * wv;
            a2 += s_ln[256 + i] * wv;
        }
        const float sc = 0.08838834764831843f;  // 1/sqrt(128)
        float bqv = bq[t];
        qs[t]       = (a0 + bqv) * sc;
        qs[128 + t] = (a1 + bqv) * sc;
        qs[256 + t] = (a2 + bqv) * sc;
    }
    __syncthreads();

    if (t < 128) {
        float a0 = 0.f, a1 = 0.f, a2 = 0.f;
        #pragma unroll 4
        for (int j = 0; j < 128; j++) {
            float wv = Wk[j*128 + t];
            a0 += qs[j]       * wv;
            a1 += qs[128 + j] * wv;
            a2 += qs[256 + j] * wv;
        }
        g_qk[b*384 + t]       = a0;
        g_qk[b*384 + 128 + t] = a1;
        g_qk[b*384 + 256 + t] = a2;

        float bkt = bk[t];
        pr[t]       = qs[t]       * bkt;
        pr[128 + t] = qs[128 + t] * bkt;
        pr[256 + t] = qs[256 + t] * bkt;
    }
    __syncthreads();
    if (t < KK) {
        float s = 0.0f;
        #pragma unroll 4
        for (int i = 0; i < 128; i++) s += pr[t*128 + i];
        g_qbk[b*4 + t] = s;
    }
}

// ============================================================
// init_q: slots init + first q. grid=BB, 256 threads.
// ============================================================
__global__ __launch_bounds__(256) void init_q(
    const float* __restrict__ noise,
    const float* __restrict__ mu,  const float* __restrict__ ls,
    const float* __restrict__ Wq,  const float* __restrict__ bq,
    const float* __restrict__ Wk,  const float* __restrict__ bk,
    const float* __restrict__ g_s, const float* __restrict__ b_s)
{
    __shared__ float h[384], s_ln[384], qs[384], pr[384];
    const int t = threadIdx.x;
    const int b = blockIdx.x;

    for (int i = t; i < 384; i += 256) {
        float v = mu[i] + expf(ls[i]) * noise[b*384 + i];
        g_slots[b*384 + i] = v;
        h[i] = v;
    }
    __syncthreads();
    q_from_slots(h, s_ln, qs, pr, Wq, bq, Wk, bk, g_s, b_s, b, t);
}

// ============================================================
// attn_tile v2: SMEM-staged tile, pair-threads-per-token logits.
// grid = BB*NTILES, 256 threads.
// ============================================================
#define TSTRIDE 140
#define ATTN_SM ((128*TSTRIDE + 6*68 + 384 + 384 + 8) * 4)

__global__ __launch_bounds__(256) void attn_tile(float* __restrict__ out_attn,
                                                 int write_attn)
{
    extern __shared__ float dyn[];
    float* tile   = dyn;                    // [128][140], halves at +0 / +68
    float* qsm    = dyn + 128*TSTRIDE;      // [(h*3+s)][68]
    float* attn_s = qsm + 6*68;             // [3][128]
    float* red    = attn_s + 384;           // [384]
    float* red2   = red + 384;              // [8]

    const int t = threadIdx.x;
    const int b    = blockIdx.x >> 3;
    const int tile_i = blockIdx.x & 7;
    const int n0   = tile_i * TILE_N;

    const float* ib = g_inputs + ((size_t)b * NN + n0) * HH;

    // stage input tile (coalesced float4)
    for (int idx = t; idx < 128*32; idx += 256) {
        int row = idx >> 5;
        int c4  = idx & 31;
        float4 v = *reinterpret_cast<const float4*>(ib + row*HH + c4*4);
        int hh = c4 >> 4;
        *reinterpret_cast<float4*>(tile + row*TSTRIDE + hh*68 + (c4 & 15)*4) = v;
    }
    // stage q with half-offset layout
    for (int idx = t; idx < 384; idx += 256) {
        int s = idx >> 7, d = idx & 127;
        qsm[((d>>6)*3 + s)*68 + (d & 63)] = g_qk[b*384 + idx];
    }
    float qb0 = g_qbk[b*4 + 0];
    float qb1 = g_qbk[b*4 + 1];
    float qb2 = g_qbk[b*4 + 2];
    __syncthreads();

    // logits: 2 threads per token, one shfl per slot
    {
        const int n = t >> 1;
        const int hh = t & 1;
        const float* tr = tile + n*TSTRIDE + hh*68;
        const float* q0 = qsm + (hh*3 + 0)*68;
        const float* q1 = qsm + (hh*3 + 1)*68;
        const float* q2 = qsm + (hh*3 + 2)*68;
        float p0 = 0.f, p1 = 0.f, p2 = 0.f;
        #pragma unroll
        for (int j = 0; j < 16; j++) {
            float4 x  = *reinterpret_cast<const float4*>(tr + j*4);
            float4 a  = *reinterpret_cast<const float4*>(q0 + j*4);
            float4 bq = *reinterpret_cast<const float4*>(q1 + j*4);
            float4 c  = *reinterpret_cast<const float4*>(q2 + j*4);
            p0 += x.x*a.x  + x.y*a.y  + x.z*a.z  + x.w*a.w;
            p1 += x.x*bq.x + x.y*bq.y + x.z*bq.z + x.w*bq.w;
            p2 += x.x*c.x  + x.y*c.y  + x.z*c.z  + x.w*c.w;
        }
        p0 += __shfl_xor_sync(0xffffffffu, p0, 1);
        p1 += __shfl_xor_sync(0xffffffffu, p1, 1);
        p2 += __shfl_xor_sync(0xffffffffu, p2, 1);
        if (hh == 0) {
            p0 += qb0; p1 += qb1; p2 += qb2;
            float mx = fmaxf(p0, fmaxf(p1, p2));
            float e0 = expf(p0 - mx), e1 = expf(p1 - mx), e2 = expf(p2 - mx);
            float inv = 1.0f / (e0 + e1 + e2);
            attn_s[n]       = e0*inv;
            attn_s[128 + n] = e1*inv;
            attn_s[256 + n] = e2*inv;
        }
    }
    __syncthreads();

    if (write_attn) {
        for (int idx = t; idx < 384; idx += 256) {
            int kk = idx >> 7;
            int n  = idx & 127;
            out_attn[b*KK*NN + kk*NN + n0 + n] = attn_s[idx];
        }
    }

    // partial attn.inputs + rowsums from SMEM tile
    const int d    = t & 127;
    const int half = t >> 7;
    const float* tcol = tile + (half*64)*TSTRIDE + (d>>6)*68 + (d & 63);
    float u0 = 0.f, u1 = 0.f, u2 = 0.f;
    float as0 = 0.f, as1 = 0.f, as2 = 0.f;
    #pragma unroll 4
    for (int n = 0; n < 64; n++) {
        float vv = tcol[n*TSTRIDE];
        int na = half*64 + n;
        float a0 = attn_s[na];
        float a1 = attn_s[128 + na];
        float a2 = attn_s[256 + na];
        u0 += a0 * vv;  u1 += a1 * vv;  u2 += a2 * vv;
        as0 += a0; as1 += a1; as2 += a2;
    }
    if (half == 1) {
        red[d] = u0; red[128+d] = u1; red[256+d] = u2;
        if (d == 0) { red2[0] = as0; red2[1] = as1; red2[2] = as2; }
    }
    __syncthreads();
    if (half == 0) {
        float* dst = g_updp + ((size_t)(b*NTILES + tile_i))*384;
        dst[d]       = u0 + red[d];
        dst[128 + d] = u1 + red[128+d];
        dst[256 + d] = u2 + red[256+d];
        if (d == 0) {
            float* ds = g_updsum + (size_t)(b*NTILES + tile_i)*4;
            ds[0] = as0 + red2[0];
            ds[1] = as1 + red2[1];
            ds[2] = as2 + red2[2];
        }
    }
}

// ============================================================
// upd_q: reduce partials, Wv/bv, GRU, LN, MLP; then next-iter q. grid=BB.
// ============================================================
__global__ __launch_bounds__(256) void upd_q(
    const float* __restrict__ Wv,  const float* __restrict__ bv,
    const float* __restrict__ Wih, const float* __restrict__ bih,
    const float* __restrict__ Whh, const float* __restrict__ bhh,
    const float* __restrict__ g_m, const float* __restrict__ b_m,
    const float* __restrict__ W1,  const float* __restrict__ b1,
    const float* __restrict__ W2,  const float* __restrict__ b2,
    const float* __restrict__ Wq,  const float* __restrict__ bq,
    const float* __restrict__ Wk,  const float* __restrict__ bk,
    const float* __restrict__ g_s, const float* __restrict__ b_s,
    float* __restrict__ out_slots, int last)
{
    __shared__ float h_prev[384];
    __shared__ float ared[384];
    __shared__ float asum[4];
    __shared__ float updf[384];
    __shared__ float gi_s[1152];
    __shared__ float gh_s[1152];
    __shared__ float snew[384];
    __shared__ float hm[384];
    __shared__ float a1_s[768];
    __shared__ float fin[384];

    const int t = threadIdx.x;
    const int lane = t & 31;
    const int warp = t >> 5;
    const int b = blockIdx.x;

    for (int i = t; i < 384; i += 256) h_prev[i] = g_slots[b*384 + i];
    if (t < 128) {
        #pragma unroll
        for (int kk = 0; kk < 3; kk++) {
            float s = 0.0f;
            const float* src = g_updp + (size_t)b*NTILES*384 + kk*128 + t;
            #pragma unroll
            for (int tl = 0; tl < NTILES; tl++) s += src[tl*384];
            ared[kk*128 + t] = s;
        }
    } else if (t < 131) {
        int s = t - 128;
        float acc = 0.0f;
        #pragma unroll
        for (int tl = 0; tl < NTILES; tl++) acc += g_updsum[(size_t)(b*NTILES + tl)*4 + s];
        asum[s] = acc;
    }
    __syncthreads();

    // updates = ared @ Wv^T + asum*bv
    if (t < 128) {
        float u0 = 0.f, u1 = 0.f, u2 = 0.f;
        const float* w = Wv + t*128;
        #pragma unroll 4
        for (int i = 0; i < 128; i++) {
            float wv = w[i];
            u0 += ared[i]       * wv;
            u1 += ared[128 + i] * wv;
            u2 += ared[256 + i] * wv;
        }
        float bvt = bv[t];
        updf[t]       = u0 + asum[0]*bvt;
        updf[128 + t] = u1 + asum[1]*bvt;
        updf[256 + t] = u2 + asum[2]*bvt;
    }
    __syncthreads();

    // GRU gate GEMMs
    for (int jj = t; jj < 384; jj += 256) {
        float ai0=0.f, ai1=0.f, ai2=0.f, ah0=0.f, ah1=0.f, ah2=0.f;
        const float* wi = Wih + jj*128;
        const float* wh = Whh + jj*128;
        #pragma unroll 4
        for (int i = 0; i < 128; i++) {
            float wiv = wi[i], whv = wh[i];
            ai0 += updf[i]        * wiv;
            ai1 += updf[128 + i]  * wiv;
            ai2 += updf[256 + i]  * wiv;
            ah0 += h_prev[i]       * whv;
            ah1 += h_prev[128 + i] * whv;
            ah2 += h_prev[256 + i] * whv;
        }
        float bi = bih[jj], bh = bhh[jj];
        gi_s[jj]        = ai0 + bi;
        gi_s[384 + jj]  = ai1 + bi;
        gi_s[768 + jj]  = ai2 + bi;
        gh_s[jj]        = ah0 + bh;
        gh_s[384 + jj]  = ah1 + bh;
        gh_s[768 + jj]  = ah2 + bh;
    }
    __syncthreads();

    if (t < 128) {
        #pragma unroll
        for (int kk = 0; kk < 3; kk++) {
            float ir  = gi_s[kk*384 + t];
            float iz  = gi_s[kk*384 + 128 + t];
            float inn = gi_s[kk*384 + 256 + t];
            float hr  = gh_s[kk*384 + t];
            float hz  = gh_s[kk*384 + 128 + t];
            float hn  = gh_s[kk*384 + 256 + t];
            float r = 1.0f / (1.0f + expf(-(ir + hr)));
            float z = 1.0f / (1.0f + expf(-(iz + hz)));
            float nn = tanhf(inn + r*hn);
            snew[kk*128 + t] = (1.0f - z)*nn + z*h_prev[kk*128 + t];
        }
    }
    __syncthreads();

    // hm = LN(snew)*g_m + b_m
    if (warp < KK) {
        float x[4];
        float s = 0.0f, sq = 0.0f;
        #pragma unroll
        for (int m = 0; m < 4; m++) {
            x[m] = snew[warp*128 + lane + 32*m];
            s += x[m]; sq += x[m]*x[m];
        }
        #pragma unroll
        for (int off = 16; off >= 1; off >>= 1) {
            s  += __shfl_xor_sync(0xffffffffu, s,  off);
            sq += __shfl_xor_sync(0xffffffffu, sq, off);
        }
        float mu   = s  * (1.0f/128.0f);
        float var  = sq * (1.0f/128.0f) - mu*mu;
        float rstd = rsqrtf(var + 1e-5f);
        #pragma unroll
        for (int m = 0; m < 4; m++) {
            int c = lane + 32*m;
            hm[warp*128 + c] = (x[m]-mu)*rstd*g_m[c] + b_m[c];
        }
    }
    __syncthreads();

    // a1 = gelu_exact(hm @ W1^T + b1)
    {
        float a0 = 0.f, a1v = 0.f, a2 = 0.f;
        const float* w = W1 + t*128;
        #pragma unroll 4
        for (int i = 0; i < 128; i++) {
            float wv = w[i];
            a0  += hm[i]       * wv;
            a1v += hm[128 + i] * wv;
            a2  += hm[256 + i] * wv;
        }
        float bb = b1[t];
        float x0 = a0 + bb, x1 = a1v + bb, x2 = a2 + bb;
        const float is2 = 0.70710678118654752f;
        a1_s[t]        = 0.5f * x0 * (1.0f + erff(x0 * is2));
        a1_s[256 + t]  = 0.5f * x1 * (1.0f + erff(x1 * is2));
        a1_s[512 + t]  = 0.5f * x2 * (1.0f + erff(x2 * is2));
    }
    __syncthreads();

    // final slots = snew + a1 @ W2^T + b2
    if (t < 128) {
        float a0 = 0.f, a1v = 0.f, a2 = 0.f;
        const float* w = W2 + t*256;
        #pragma unroll 4
        for (int i = 0; i < 256; i++) {
            float wv = w[i];
            a0  += a1_s[i]       * wv;
            a1v += a1_s[256 + i] * wv;
            a2  += a1_s[512 + i] * wv;
        }
        float bb = b2[t];
        int base = b*384;
        float f0 = snew[t]       + a0  + bb;
        float f1 = snew[128 + t] + a1v + bb;
        float f2 = snew[256 + t] + a2  + bb;
        fin[t] = f0; fin[128 + t] = f1; fin[256 + t] = f2;
        g_slots[base + t]       = f0;
        g_slots[base + 128 + t] = f1;
        g_slots[base + 256 + t] = f2;
        if (last) {
            out_slots[base + t]       = f0;
            out_slots[base + 128 + t] = f1;
            out_slots[base + 256 + t] = f2;
        }
    }
    __syncthreads();

    if (!last) {
        // next iteration's q (reuse buffers: gi_s space as scratch)
        q_from_slots(fin, gi_s, gi_s + 384, gi_s + 768,
                     Wq, bq, Wk, bk, g_s, b_s, b, t);
    }
}

// ============================================================
extern "C" void kernel_launch(void* const* d_in, const int* in_sizes, int n_in,
                              void* d_out, int out_size)
{
    const float* patch   = (const float*)d_in[0];
    const float* noise   = (const float*)d_in[1];
    const float* slot_mu = (const float*)d_in[2];
    const float* slot_ls = (const float*)d_in[3];
    const float* Wp  = (const float*)d_in[4];
    const float* bp  = (const float*)d_in[5];
    const float* g_in= (const float*)d_in[6];
    const float* b_in= (const float*)d_in[7];
    const float* Wq  = (const float*)d_in[8];
    const float* bq  = (const float*)d_in[9];
    const float* Wk  = (const float*)d_in[10];
    const float* bk  = (const float*)d_in[11];
    const float* Wv  = (const float*)d_in[12];
    const float* bv  = (const float*)d_in[13];
    const float* Wih = (const float*)d_in[14];
    const float* bih = (const float*)d_in[15];
    const float* Whh = (const float*)d_in[16];
    const float* bhh = (const float*)d_in[17];
    const float* g_s = (const float*)d_in[18];
    const float* b_s = (const float*)d_in[19];
    const float* W1  = (const float*)d_in[20];
    const float* b1  = (const float*)d_in[21];
    const float* W2  = (const float*)d_in[22];
    const float* b2  = (const float*)d_in[23];
    const float* g_m = (const float*)d_in[24];
    const float* b_m = (const float*)d_in[25];

    float* out       = (float*)d_out;
    float* out_slots = out;                     // B*K*H = 49152
    float* out_attn  = out + BB*KK*HH;          // B*K*N = 393216

    cudaFuncSetAttribute(proj_ln, cudaFuncAttributeMaxDynamicSharedMemorySize, SM1_BYTES);
    cudaFuncSetAttribute(attn_tile, cudaFuncAttributeMaxDynamicSharedMemorySize, ATTN_SM);

    proj_ln<<<(BB*NN)/128, 256, SM1_BYTES>>>(patch, Wp, bp, g_in, b_in);
    init_q<<<BB, 256>>>(noise, slot_mu, slot_ls, Wq, bq, Wk, bk, g_s, b_s);
    for (int it = 0; it < 3; it++) {
        attn_tile<<<BB*NTILES, 256, ATTN_SM>>>(out_attn, it == 2 ? 1 : 0);
        upd_q<<<BB, 256>>>(Wv, bv, Wih, bih, Whh, bhh, g_m, b_m,
                           W1, b1, W2, b2, Wq, bq, Wk, bk, g_s, b_s,
                           out_slots, it == 2 ? 1 : 0);
    }
}

// round 12
// speedup vs baseline: 3.1118x; 1.3078x over previous
#include <cuda_runtime.h>
#include <cuda_bf16.h>
#include <math.h>

#define BB   128
#define NN   1024
#define DIN  192
#define HH   128
#define KK   3
#define NTILES 8
#define TILE_N 128
#define UPD_THREADS 384

typedef unsigned int u32;

// -------- device scratch (no allocations allowed) --------
__device__ float g_inputs[(size_t)BB*NN*HH];   // 64 MB, LN'ed projected inputs
__device__ float g_slots[BB*KK*HH];
__device__ float g_qk[BB*KK*HH];               // q' = Wk^T (scale*q)
__device__ float g_qbk[BB*4];                  // (scale*q) . bk per slot
__device__ float g_updp[BB*NTILES*KK*HH];      // partial attn.inputs
__device__ float g_updsum[BB*NTILES*4];        // partial attn row sums

// transposed weights (coalesced thread-per-output access)
__device__ float g_WihT[128*384];
__device__ float g_WhhT[128*384];
__device__ float g_WvT[128*128];
__device__ float g_W1T[128*256];
__device__ float g_W2T[256*128];
__device__ float g_WqT[128*128];

// bf16 split helpers
__device__ __forceinline__ void bsplit(float x, float& h, float& r) {
    __nv_bfloat16 b = __float2bfloat16_rn(x);
    h = __bfloat162float(b);
    r = x - h;
}
__device__ __forceinline__ u32 pk2(float lo, float hi) {
    __nv_bfloat162 t = __floats2bfloat162_rn(lo, hi);
    return *reinterpret_cast<u32*>(&t);
}

__device__ __forceinline__ void mma16816(float* c, u32 a0, u32 a1, u32 a2, u32 a3,
                                         u32 b0, u32 b1) {
    asm volatile(
        "mma.sync.aligned.m16n8k16.row.col.f32.bf16.bf16.f32 "
        "{%0,%1,%2,%3}, {%4,%5,%6,%7}, {%8,%9}, {%0,%1,%2,%3};"
        : "+f"(c[0]), "+f"(c[1]), "+f"(c[2]), "+f"(c[3])
        : "r"(a0), "r"(a1), "r"(a2), "r"(a3), "r"(b0), "r"(b1));
}

// ============================================================
// transpose_all: one-time weight transposes into device scratch.
// grid covers 384*128 = 49152 elements.
// ============================================================
__global__ void transpose_all(
    const float* __restrict__ Wih, const float* __restrict__ Whh,
    const float* __restrict__ Wv,  const float* __restrict__ W1,
    const float* __restrict__ W2,  const float* __restrict__ Wq)
{
    int idx = blockIdx.x * 256 + threadIdx.x;
    if (idx < 384*128) {            // Wih/Whh: (384,128) -> T (128,384)
        int j = idx >> 7, i = idx & 127;
        g_WihT[i*384 + j] = Wih[idx];
        g_WhhT[i*384 + j] = Whh[idx];
    }
    if (idx < 256*128) {            // W1: (256,128) -> T (128,256)
        int j = idx >> 7, i = idx & 127;
        g_W1T[i*256 + j] = W1[idx];
    }
    if (idx < 128*256) {            // W2: (128,256) -> T (256,128)
        int j = idx >> 8, i = idx & 255;
        g_W2T[i*128 + j] = W2[idx];
    }
    if (idx < 128*128) {            // Wv, Wq: (128,128) -> T
        int j = idx >> 7, i = idx & 127;
        g_WvT[i*128 + j] = Wv[idx];
        g_WqT[i*128 + j] = Wq[idx];
    }
}

// ============================================================
// Kernel 1: inputs = LN(patch @ Wp^T + bp) via bf16x3 mma.sync.
// 128 rows/CTA, 1024 CTAs, 256 threads (8 warps, 16 rows each).
// ============================================================
#define RSTRIDE 400
#define AH_OFF  0
#define AL_OFF  (128*RSTRIDE)
#define WH_OFF  (2*128*RSTRIDE)
#define WL_OFF  (3*128*RSTRIDE)
#define PAR_OFF (4*128*RSTRIDE)
#define SM1_BYTES (PAR_OFF + 3*128*4)

__global__ __launch_bounds__(256) void proj_ln(
    const float* __restrict__ patch,
    const float* __restrict__ Wp, const float* __restrict__ bp,
    const float* __restrict__ g_in, const float* __restrict__ b_in)
{
    extern __shared__ char smc[];
    float* bpS = reinterpret_cast<float*>(smc + PAR_OFF);
    float* gS  = bpS + 128;
    float* bS  = gS + 128;

    const int t    = threadIdx.x;
    const int warp = t >> 5;
    const int lane = t & 31;
    const int g    = lane >> 2;
    const int tig  = lane & 3;
    const long rowbase = (long)blockIdx.x * 128;

    if (t < 128) { bpS[t] = bp[t]; gS[t] = g_in[t]; bS[t] = b_in[t]; }

    for (int idx = t; idx < 128*48; idx += 256) {
        int row = idx / 48;
        int c4  = idx % 48;
        float4 gv = *reinterpret_cast<const float4*>(patch + (rowbase + row)*DIN + c4*4);
        float h0,h1,h2,h3,r0,r1,r2,r3;
        bsplit(gv.x,h0,r0); bsplit(gv.y,h1,r1); bsplit(gv.z,h2,r2); bsplit(gv.w,h3,r3);
        int off = row*RSTRIDE + c4*8;
        *reinterpret_cast<uint2*>(smc + AH_OFF + off) = make_uint2(pk2(h0,h1), pk2(h2,h3));
        *reinterpret_cast<uint2*>(smc + AL_OFF + off) = make_uint2(pk2(r0,r1), pk2(r2,r3));
    }
    for (int idx = t; idx < 128*48; idx += 256) {
        int row = idx / 48;
        int c4  = idx % 48;
        float4 gv = *reinterpret_cast<const float4*>(Wp + row*DIN + c4*4);
        float h0,h1,h2,h3,r0,r1,r2,r3;
        bsplit(gv.x,h0,r0); bsplit(gv.y,h1,r1); bsplit(gv.z,h2,r2); bsplit(gv.w,h3,r3);
        int off = row*RSTRIDE + c4*8;
        *reinterpret_cast<uint2*>(smc + WH_OFF + off) = make_uint2(pk2(h0,h1), pk2(h2,h3));
        *reinterpret_cast<uint2*>(smc + WL_OFF + off) = make_uint2(pk2(r0,r1), pk2(r2,r3));
    }
    __syncthreads();

    float acc[16][4];
    #pragma unroll
    for (int nf = 0; nf < 16; nf++)
        #pragma unroll
        for (int i = 0; i < 4; i++) acc[nf][i] = 0.0f;

    const int r0 = 16*warp + g;
    const int aoff0 = r0 * RSTRIDE + tig * 4;

    #pragma unroll
    for (int pass = 0; pass < 3; pass++) {
        const char* A = smc + (pass == 1 ? AL_OFF : AH_OFF);
        const char* B = smc + (pass == 2 ? WL_OFF : WH_OFF);
        #pragma unroll
        for (int ks = 0; ks < 12; ks++) {
            int ao = aoff0 + ks*32;
            u32 a0 = *reinterpret_cast<const u32*>(A + ao);
            u32 a1 = *reinterpret_cast<const u32*>(A + ao + 8*RSTRIDE);
            u32 a2 = *reinterpret_cast<const u32*>(A + ao + 16);
            u32 a3 = *reinterpret_cast<const u32*>(A + ao + 8*RSTRIDE + 16);
            #pragma unroll
            for (int nf = 0; nf < 16; nf++) {
                int bo = (8*nf + g)*RSTRIDE + ks*32 + tig*4;
                u32 b0 = *reinterpret_cast<const u32*>(B + bo);
                u32 b1 = *reinterpret_cast<const u32*>(B + bo + 16);
                mma16816(acc[nf], a0, a1, a2, a3, b0, b1);
            }
        }
    }

    #pragma unroll
    for (int nf = 0; nf < 16; nf++) {
        int c = 8*nf + 2*tig;
        acc[nf][0] += bpS[c];   acc[nf][1] += bpS[c+1];
        acc[nf][2] += bpS[c];   acc[nf][3] += bpS[c+1];
    }
    float s0 = 0.f, q0 = 0.f, s1 = 0.f, q1 = 0.f;
    #pragma unroll
    for (int nf = 0; nf < 16; nf++) {
        s0 += acc[nf][0] + acc[nf][1];
        q0 += acc[nf][0]*acc[nf][0] + acc[nf][1]*acc[nf][1];
        s1 += acc[nf][2] + acc[nf][3];
        q1 += acc[nf][2]*acc[nf][2] + acc[nf][3]*acc[nf][3];
    }
    #pragma unroll
    for (int m = 1; m <= 2; m <<= 1) {
        s0 += __shfl_xor_sync(0xffffffffu, s0, m);
        q0 += __shfl_xor_sync(0xffffffffu, q0, m);
        s1 += __shfl_xor_sync(0xffffffffu, s1, m);
        q1 += __shfl_xor_sync(0xffffffffu, q1, m);
    }
    float mu0 = s0*(1.0f/128.0f), var0 = q0*(1.0f/128.0f) - mu0*mu0;
    float mu1 = s1*(1.0f/128.0f), var1 = q1*(1.0f/128.0f) - mu1*mu1;
    float rs0 = rsqrtf(var0 + 1e-5f);
    float rs1 = rsqrtf(var1 + 1e-5f);

    float* out0 = g_inputs + (rowbase + r0) * HH;
    float* out1 = g_inputs + (rowbase + r0 + 8) * HH;
    #pragma unroll
    for (int nf = 0; nf < 16; nf++) {
        int c = 8*nf + 2*tig;
        float2 y0 = make_float2((acc[nf][0]-mu0)*rs0*gS[c]   + bS[c],
                                (acc[nf][1]-mu0)*rs0*gS[c+1] + bS[c+1]);
        float2 y1 = make_float2((acc[nf][2]-mu1)*rs1*gS[c]   + bS[c],
                                (acc[nf][3]-mu1)*rs1*gS[c+1] + bS[c+1]);
        *reinterpret_cast<float2*>(out0 + c) = y0;
        *reinterpret_cast<float2*>(out1 + c) = y1;
    }
}

// ============================================================
// q computation from slots in smem `h` -> g_qk/g_qbk (UPD_THREADS threads).
// ============================================================
__device__ __forceinline__ void q_from_slots(
    const float* __restrict__ h,      // smem [384]
    float* __restrict__ s_ln, float* __restrict__ qs, float* __restrict__ pr,
    const float* __restrict__ bq,
    const float* __restrict__ Wk,  const float* __restrict__ bk,
    const float* __restrict__ g_s, const float* __restrict__ b_s,
    int b, int t)
{
    const int lane = t & 31;
    const int warp = t >> 5;

    if (warp < KK) {
        float x[4];
        float s = 0.0f, sq = 0.0f;
        #pragma unroll
        for (int m = 0; m < 4; m++) {
            x[m] = h[warp*128 + lane + 32*m];
            s += x[m]; sq += x[m]*x[m];
        }
        #pragma unroll
        for (int off = 16; off >= 1; off >>= 1) {
            s  += __shfl_xor_sync(0xffffffffu, s,  off);
            sq += __shfl_xor_sync(0xffffffffu, sq, off);
        }
        float mu   = s  * (1.0f/128.0f);
        float var  = sq * (1.0f/128.0f) - mu*mu;
        float rstd = rsqrtf(var + 1e-5f);
        #pragma unroll
        for (int m = 0; m < 4; m++) {
            int c = lane + 32*m;
            s_ln[warp*128 + c] = (x[m]-mu)*rstd*g_s[c] + b_s[c];
        }
    }
    __syncthreads();

    if (t < 128) {
        float a0 = 0.f, a1 = 0.f, a2 = 0.f;
        #pragma unroll 8
        for (int i = 0; i < 128; i++) {
            float wv = g_WqT[i*128 + t];
            a0 += s_ln[i]       * wv;
            a1 += s_ln[128 + i] * wv;
            a2 += s_ln[256 + i] * wv;
        }
        const float sc = 0.08838834764831843f;  // 1/sqrt(128)
        float bqv = bq[t];
        qs[t]       = (a0 + bqv) * sc;
        qs[128 + t] = (a1 + bqv) * sc;
        qs[256 + t] = (a2 + bqv) * sc;
    }
    __syncthreads();

    if (t < 128) {
        float a0 = 0.f, a1 = 0.f, a2 = 0.f;
        #pragma unroll 8
        for (int j = 0; j < 128; j++) {
            float wv = Wk[j*128 + t];
            a0 += qs[j]       * wv;
            a1 += qs[128 + j] * wv;
            a2 += qs[256 + j] * wv;
        }
        g_qk[b*384 + t]       = a0;
        g_qk[b*384 + 128 + t] = a1;
        g_qk[b*384 + 256 + t] = a2;

        float bkt = bk[t];
        pr[t]       = qs[t]       * bkt;
        pr[128 + t] = qs[128 + t] * bkt;
        pr[256 + t] = qs[256 + t] * bkt;
    }
    __syncthreads();
    if (t < KK) {
        float s = 0.0f;
        #pragma unroll 8
        for (int i = 0; i < 128; i++) s += pr[t*128 + i];
        g_qbk[b*4 + t] = s;
    }
}

// ============================================================
// init_q: slots init + first q. grid=BB, UPD_THREADS threads.
// ============================================================
__global__ __launch_bounds__(UPD_THREADS) void init_q(
    const float* __restrict__ noise,
    const float* __restrict__ mu,  const float* __restrict__ ls,
    const float* __restrict__ bq,
    const float* __restrict__ Wk,  const float* __restrict__ bk,
    const float* __restrict__ g_s, const float* __restrict__ b_s)
{
    __shared__ float h[384], s_ln[384], qs[384], pr[384];
    const int t = threadIdx.x;
    const int b = blockIdx.x;

    if (t < 384) {
        float v = mu[t] + expf(ls[t]) * noise[b*384 + t];
        g_slots[b*384 + t] = v;
        h[t] = v;
    }
    __syncthreads();
    q_from_slots(h, s_ln, qs, pr, bq, Wk, bk, g_s, b_s, b, t);
}

// ============================================================
// attn_tile v2: SMEM-staged tile, pair-threads-per-token logits.
// grid = BB*NTILES, 256 threads.
// ============================================================
#define TSTRIDE 140
#define ATTN_SM ((128*TSTRIDE + 6*68 + 384 + 384 + 8) * 4)

__global__ __launch_bounds__(256) void attn_tile(float* __restrict__ out_attn,
                                                 int write_attn)
{
    extern __shared__ float dyn[];
    float* tile   = dyn;                    // [128][140], halves at +0 / +68
    float* qsm    = dyn + 128*TSTRIDE;      // [(h*3+s)][68]
    float* attn_s = qsm + 6*68;             // [3][128]
    float* red    = attn_s + 384;           // [384]
    float* red2   = red + 384;              // [8]

    const int t = threadIdx.x;
    const int b    = blockIdx.x >> 3;
    const int tile_i = blockIdx.x & 7;
    const int n0   = tile_i * TILE_N;

    const float* ib = g_inputs + ((size_t)b * NN + n0) * HH;

    for (int idx = t; idx < 128*32; idx += 256) {
        int row = idx >> 5;
        int c4  = idx & 31;
        float4 v = *reinterpret_cast<const float4*>(ib + row*HH + c4*4);
        int hh = c4 >> 4;
        *reinterpret_cast<float4*>(tile + row*TSTRIDE + hh*68 + (c4 & 15)*4) = v;
    }
    for (int idx = t; idx < 384; idx += 256) {
        int s = idx >> 7, d = idx & 127;
        qsm[((d>>6)*3 + s)*68 + (d & 63)] = g_qk[b*384 + idx];
    }
    float qb0 = g_qbk[b*4 + 0];
    float qb1 = g_qbk[b*4 + 1];
    float qb2 = g_qbk[b*4 + 2];
    __syncthreads();

    {
        const int n = t >> 1;
        const int hh = t & 1;
        const float* tr = tile + n*TSTRIDE + hh*68;
        const float* q0 = qsm + (hh*3 + 0)*68;
        const float* q1 = qsm + (hh*3 + 1)*68;
        const float* q2 = qsm + (hh*3 + 2)*68;
        float p0 = 0.f, p1 = 0.f, p2 = 0.f;
        #pragma unroll
        for (int j = 0; j < 16; j++) {
            float4 x  = *reinterpret_cast<const float4*>(tr + j*4);
            float4 a  = *reinterpret_cast<const float4*>(q0 + j*4);
            float4 bq = *reinterpret_cast<const float4*>(q1 + j*4);
            float4 c  = *reinterpret_cast<const float4*>(q2 + j*4);
            p0 += x.x*a.x  + x.y*a.y  + x.z*a.z  + x.w*a.w;
            p1 += x.x*bq.x + x.y*bq.y + x.z*bq.z + x.w*bq.w;
            p2 += x.x*c.x  + x.y*c.y  + x.z*c.z  + x.w*c.w;
        }
        p0 += __shfl_xor_sync(0xffffffffu, p0, 1);
        p1 += __shfl_xor_sync(0xffffffffu, p1, 1);
        p2 += __shfl_xor_sync(0xffffffffu, p2, 1);
        if (hh == 0) {
            p0 += qb0; p1 += qb1; p2 += qb2;
            float mx = fmaxf(p0, fmaxf(p1, p2));
            float e0 = expf(p0 - mx), e1 = expf(p1 - mx), e2 = expf(p2 - mx);
            float inv = 1.0f / (e0 + e1 + e2);
            attn_s[n]       = e0*inv;
            attn_s[128 + n] = e1*inv;
            attn_s[256 + n] = e2*inv;
        }
    }
    __syncthreads();

    if (write_attn) {
        for (int idx = t; idx < 384; idx += 256) {
            int kk = idx >> 7;
            int n  = idx & 127;
            out_attn[b*KK*NN + kk*NN + n0 + n] = attn_s[idx];
        }
    }

    const int d    = t & 127;
    const int half = t >> 7;
    const float* tcol = tile + (half*64)*TSTRIDE + (d>>6)*68 + (d & 63);
    float u0 = 0.f, u1 = 0.f, u2 = 0.f;
    float as0 = 0.f, as1 = 0.f, as2 = 0.f;
    #pragma unroll 4
    for (int n = 0; n < 64; n++) {
        float vv = tcol[n*TSTRIDE];
        int na = half*64 + n;
        float a0 = attn_s[na];
        float a1 = attn_s[128 + na];
        float a2 = attn_s[256 + na];
        u0 += a0 * vv;  u1 += a1 * vv;  u2 += a2 * vv;
        as0 += a0; as1 += a1; as2 += a2;
    }
    if (half == 1) {
        red[d] = u0; red[128+d] = u1; red[256+d] = u2;
        if (d == 0) { red2[0] = as0; red2[1] = as1; red2[2] = as2; }
    }
    __syncthreads();
    if (half == 0) {
        float* dst = g_updp + ((size_t)(b*NTILES + tile_i))*384;
        dst[d]       = u0 + red[d];
        dst[128 + d] = u1 + red[128+d];
        dst[256 + d] = u2 + red[256+d];
        if (d == 0) {
            float* ds = g_updsum + (size_t)(b*NTILES + tile_i)*4;
            ds[0] = as0 + red2[0];
            ds[1] = as1 + red2[1];
            ds[2] = as2 + red2[2];
        }
    }
}

// ============================================================
// upd_q: reduce partials, Wv/bv, GRU, LN, MLP; then next-iter q.
// grid=BB, UPD_THREADS threads, transposed (coalesced) weights.
// ============================================================
__global__ __launch_bounds__(UPD_THREADS) void upd_q(
    const float* __restrict__ bv,
    const float* __restrict__ bih, const float* __restrict__ bhh,
    const float* __restrict__ g_m, const float* __restrict__ b_m,
    const float* __restrict__ b1,  const float* __restrict__ b2,
    const float* __restrict__ bq,
    const float* __restrict__ Wk,  const float* __restrict__ bk,
    const float* __restrict__ g_s, const float* __restrict__ b_s,
    float* __restrict__ out_slots, int last)
{
    __shared__ float h_prev[384];
    __shared__ float ared[384];
    __shared__ float asum[4];
    __shared__ float updf[384];
    __shared__ float gi_s[1152];
    __shared__ float gh_s[1152];
    __shared__ float snew[384];
    __shared__ float hm[384];
    __shared__ float a1_s[768];
    __shared__ float fin[384];

    const int t = threadIdx.x;
    const int lane = t & 31;
    const int warp = t >> 5;
    const int b = blockIdx.x;

    if (t < 384) h_prev[t] = g_slots[b*384 + t];
    if (t < 128) {
        #pragma unroll
        for (int kk = 0; kk < 3; kk++) {
            float s = 0.0f;
            const float* src = g_updp + (size_t)b*NTILES*384 + kk*128 + t;
            #pragma unroll
            for (int tl = 0; tl < NTILES; tl++) s += src[tl*384];
            ared[kk*128 + t] = s;
        }
    } else if (t < 131) {
        int s = t - 128;
        float acc = 0.0f;
        #pragma unroll
        for (int tl = 0; tl < NTILES; tl++) acc += g_updsum[(size_t)(b*NTILES + tl)*4 + s];
        asum[s] = acc;
    }
    __syncthreads();

    // updates = ared @ Wv^T + asum*bv   (coalesced WvT)
    if (t < 128) {
        float u0 = 0.f, u1 = 0.f, u2 = 0.f;
        #pragma unroll 8
        for (int i = 0; i < 128; i++) {
            float wv = g_WvT[i*128 + t];
            u0 += ared[i]       * wv;
            u1 += ared[128 + i] * wv;
            u2 += ared[256 + i] * wv;
        }
        float bvt = bv[t];
        updf[t]       = u0 + asum[0]*bvt;
        updf[128 + t] = u1 + asum[1]*bvt;
        updf[256 + t] = u2 + asum[2]*bvt;
    }
    __syncthreads();

    // GRU gate GEMMs (coalesced WihT/WhhT, one output per thread)
    {
        float ai0=0.f, ai1=0.f, ai2=0.f, ah0=0.f, ah1=0.f, ah2=0.f;
        #pragma unroll 8
        for (int i = 0; i < 128; i++) {
            float wiv = g_WihT[i*384 + t];
            float whv = g_WhhT[i*384 + t];
            ai0 += updf[i]        * wiv;
            ai1 += updf[128 + i]  * wiv;
            ai2 += updf[256 + i]  * wiv;
            ah0 += h_prev[i]       * whv;
            ah1 += h_prev[128 + i] * whv;
            ah2 += h_prev[256 + i] * whv;
        }
        float bi = bih[t], bh = bhh[t];
        gi_s[t]        = ai0 + bi;
        gi_s[384 + t]  = ai1 + bi;
        gi_s[768 + t]  = ai2 + bi;
        gh_s[t]        = ah0 + bh;
        gh_s[384 + t]  = ah1 + bh;
        gh_s[768 + t]  = ah2 + bh;
    }
    __syncthreads();

    if (t < 128) {
        #pragma unroll
        for (int kk = 0; kk < 3; kk++) {
            float ir  = gi_s[kk*384 + t];
            float iz  = gi_s[kk*384 + 128 + t];
            float inn = gi_s[kk*384 + 256 + t];
            float hr  = gh_s[kk*384 + t];
            float hz  = gh_s[kk*384 + 128 + t];
            float hn  = gh_s[kk*384 + 256 + t];
            float r = 1.0f / (1.0f + expf(-(ir + hr)));
            float z = 1.0f / (1.0f + expf(-(iz + hz)));
            float nn = tanhf(inn + r*hn);
            snew[kk*128 + t] = (1.0f - z)*nn + z*h_prev[kk*128 + t];
        }
    }
    __syncthreads();

    // hm = LN(snew)*g_m + b_m
    if (warp < KK) {
        float x[4];
        float s = 0.0f, sq = 0.0f;
        #pragma unroll
        for (int m = 0; m < 4; m++) {
            x[m] = snew[warp*128 + lane + 32*m];
            s += x[m]; sq += x[m]*x[m];
        }
        #pragma unroll
        for (int off = 16; off >= 1; off >>= 1) {
            s  += __shfl_xor_sync(0xffffffffu, s,  off);
            sq += __shfl_xor_sync(0xffffffffu, sq, off);
        }
        float mu   = s  * (1.0f/128.0f);
        float var  = sq * (1.0f/128.0f) - mu*mu;
        float rstd = rsqrtf(var + 1e-5f);
        #pragma unroll
        for (int m = 0; m < 4; m++) {
            int c = lane + 32*m;
            hm[warp*128 + c] = (x[m]-mu)*rstd*g_m[c] + b_m[c];
        }
    }
    __syncthreads();

    // a1 = gelu_exact(hm @ W1^T + b1)   (coalesced W1T, 256 outputs)
    if (t < 256) {
        float a0 = 0.f, a1v = 0.f, a2 = 0.f;
        #pragma unroll 8
        for (int i = 0; i < 128; i++) {
            float wv = g_W1T[i*256 + t];
            a0  += hm[i]       * wv;
            a1v += hm[128 + i] * wv;
            a2  += hm[256 + i] * wv;
        }
        float bb = b1[t];
        float x0 = a0 + bb, x1 = a1v + bb, x2 = a2 + bb;
        const float is2 = 0.70710678118654752f;
        a1_s[t]        = 0.5f * x0 * (1.0f + erff(x0 * is2));
        a1_s[256 + t]  = 0.5f * x1 * (1.0f + erff(x1 * is2));
        a1_s[512 + t]  = 0.5f * x2 * (1.0f + erff(x2 * is2));
    }
    __syncthreads();

    // final slots = snew + a1 @ W2^T + b2   (coalesced W2T)
    if (t < 128) {
        float a0 = 0.f, a1v = 0.f, a2 = 0.f;
        #pragma unroll 8
        for (int i = 0; i < 256; i++) {
            float wv = g_W2T[i*128 + t];
            a0  += a1_s[i]       * wv;
            a1v += a1_s[256 + i] * wv;
            a2  += a1_s[512 + i] * wv;
        }
        float bb = b2[t];
        int base = b*384;
        float f0 = snew[t]       + a0  + bb;
        float f1 = snew[128 + t] + a1v + bb;
        float f2 = snew[256 + t] + a2  + bb;
        fin[t] = f0; fin[128 + t] = f1; fin[256 + t] = f2;
        g_slots[base + t]       = f0;
        g_slots[base + 128 + t] = f1;
        g_slots[base + 256 + t] = f2;
        if (last) {
            out_slots[base + t]       = f0;
            out_slots[base + 128 + t] = f1;
            out_slots[base + 256 + t] = f2;
        }
    }
    __syncthreads();

    if (!last) {
        q_from_slots(fin, gi_s, gi_s + 384, gi_s + 768,
                     bq, Wk, bk, g_s, b_s, b, t);
    }
}

// ============================================================
extern "C" void kernel_launch(void* const* d_in, const int* in_sizes, int n_in,
                              void* d_out, int out_size)
{
    const float* patch   = (const float*)d_in[0];
    const float* noise   = (const float*)d_in[1];
    const float* slot_mu = (const float*)d_in[2];
    const float* slot_ls = (const float*)d_in[3];
    const float* Wp  = (const float*)d_in[4];
    const float* bp  = (const float*)d_in[5];
    const float* g_in= (const float*)d_in[6];
    const float* b_in= (const float*)d_in[7];
    const float* Wq  = (const float*)d_in[8];
    const float* bq  = (const float*)d_in[9];
    const float* Wk  = (const float*)d_in[10];
    const float* bk  = (const float*)d_in[11];
    const float* Wv  = (const float*)d_in[12];
    const float* bv  = (const float*)d_in[13];
    const float* Wih = (const float*)d_in[14];
    const float* bih = (const float*)d_in[15];
    const float* Whh = (const float*)d_in[16];
    const float* bhh = (const float*)d_in[17];
    const float* g_s = (const float*)d_in[18];
    const float* b_s = (const float*)d_in[19];
    const float* W1  = (const float*)d_in[20];
    const float* b1  = (const float*)d_in[21];
    const float* W2  = (const float*)d_in[22];
    const float* b2  = (const float*)d_in[23];
    const float* g_m = (const float*)d_in[24];
    const float* b_m = (const float*)d_in[25];

    float* out       = (float*)d_out;
    float* out_slots = out;                     // B*K*H = 49152
    float* out_attn  = out + BB*KK*HH;          // B*K*N = 393216

    cudaFuncSetAttribute(proj_ln, cudaFuncAttributeMaxDynamicSharedMemorySize, SM1_BYTES);
    cudaFuncSetAttribute(attn_tile, cudaFuncAttributeMaxDynamicSharedMemorySize, ATTN_SM);

    transpose_all<<<192, 256>>>(Wih, Whh, Wv, W1, W2, Wq);
    proj_ln<<<(BB*NN)/128, 256, SM1_BYTES>>>(patch, Wp, bp, g_in, b_in);
    init_q<<<BB, UPD_THREADS>>>(noise, slot_mu, slot_ls, bq, Wk, bk, g_s, b_s);
    for (int it = 0; it < 3; it++) {
        attn_tile<<<BB*NTILES, 256, ATTN_SM>>>(out_attn, it == 2 ? 1 : 0);
        upd_q<<<BB, UPD_THREADS>>>(bv, bih, bhh, g_m, b_m, b1, b2,
                                   bq, Wk, bk, g_s, b_s,
                                   out_slots, it == 2 ? 1 : 0);
    }
}